// round 12
// baseline (speedup 1.0000x reference)
#include <cuda_runtime.h>
#include <cuda_bf16.h>
#include <stdint.h>
#include <math.h>

#define NN 50000
#define NE 800000
#define IND 64
#define ED 16
#define HID 128
#define GG 128
#define EPSV 1e-5f
#define ASTR 132   // padded smem row stride (bf16 elems)

// ---------------- scratch (no allocations allowed) ----------------
__device__ float d_h[(size_t)NN * HID];   // node features
__device__ float d_t[(size_t)NN * HID];   // aggr / mlp buffer
__device__ float d_g[GG * HID];           // pooled per-graph
__device__ int   d_off[GG + 1];           // graph segment offsets

// ---------------- graph offsets (batch is sorted int32) ----------------
__global__ void offsets_kernel(const int* __restrict__ batch) {
    int g = blockIdx.x * blockDim.x + threadIdx.x;
    if (g > GG) return;
    int lo = 0, hi = NN;
    while (lo < hi) {
        int mid = (lo + hi) >> 1;
        if (batch[mid] < g) lo = mid + 1; else hi = mid;
    }
    d_off[g] = lo;
}

// ---------------- packed f32x2 helpers ----------------
__device__ __forceinline__ unsigned long long pack2(float lo, float hi) {
    unsigned long long r;
    asm("mov.b64 %0, {%1, %2};" : "=l"(r) : "r"(__float_as_uint(lo)), "r"(__float_as_uint(hi)));
    return r;
}
__device__ __forceinline__ unsigned long long bcast2(float a) {
    unsigned long long r;
    unsigned int u = __float_as_uint(a);
    asm("mov.b64 %0, {%1, %1};" : "=l"(r) : "r"(u));
    return r;
}
__device__ __forceinline__ void unpack2(unsigned long long v, float& lo, float& hi) {
    unsigned int a, b;
    asm("mov.b64 {%0, %1}, %2;" : "=r"(a), "=r"(b) : "l"(v));
    lo = __uint_as_float(a); hi = __uint_as_float(b);
}
#define FMA2(ACC, AA, WW) asm("fma.rn.f32x2 %0, %1, %2, %0;" : "+l"(ACC) : "l"(AA), "l"(WW))
#define ADD2(D, A, B)     asm("add.rn.f32x2 %0, %1, %2;"     : "=l"(D)  : "l"(A), "l"(B))

// ---------------- edge message + vector-red scatter (f32x2 + prefetch) ----------------
// aggr[dst] += relu(h[src] + ea@W + b)   (aggr pre-seeded with h)
__global__ __launch_bounds__(256, 2) void msg_red(
    const int* __restrict__ ei, const float* __restrict__ ea,
    const float* __restrict__ ew, const float* __restrict__ eb,
    const float* __restrict__ h, float* __restrict__ aggr)
{
    int tid = threadIdx.x, lane = tid & 31, warp = tid >> 5;
    // each lane owns 4 output columns, packed as 2 col-pairs per k-row
    unsigned long long w01[ED], w23[ED];
    #pragma unroll
    for (int k = 0; k < ED; k++) {
        float4 w = ((const float4*)ew)[k * 32 + lane];
        w01[k] = pack2(w.x, w.y);
        w23[k] = pack2(w.z, w.w);
    }
    float4 bias = ((const float4*)eb)[lane];
    unsigned long long b01 = pack2(bias.x, bias.y);
    unsigned long long b23 = pack2(bias.z, bias.w);

    int gw = blockIdx.x * 8 + warp;
    int nwarps = gridDim.x * 8;
    const float4* h4 = (const float4*)h;

    int e = gw;
    if (e >= NE) return;
    // prologue: load current edge
    int src = ei[e], dst = ei[NE + e];
    const float4* ep = (const float4*)(ea + (size_t)e * ED);
    float4 e0 = ep[0], e1 = ep[1], e2 = ep[2], e3 = ep[3];
    float4 hv = h4[(size_t)src * 32 + lane];

    while (true) {
        // prefetch next edge (overlaps with current compute)
        int en = e + nwarps;
        bool more = en < NE;
        int sn = 0, dn = 0;
        float4 n0, n1, n2, n3, hn;
        if (more) {
            sn = ei[en]; dn = ei[NE + en];
            const float4* epn = (const float4*)(ea + (size_t)en * ED);
            n0 = epn[0]; n1 = epn[1]; n2 = epn[2]; n3 = epn[3];
            hn = h4[(size_t)sn * 32 + lane];
        }

        // compute current: 32 FFMA2 on fma pipe + 16 packs on alu pipe
        float a[16] = { e0.x, e0.y, e0.z, e0.w, e1.x, e1.y, e1.z, e1.w,
                        e2.x, e2.y, e2.z, e2.w, e3.x, e3.y, e3.z, e3.w };
        unsigned long long m01a = b01, m23a = b23;
        unsigned long long m01b = 0ull, m23b = 0ull;
        #pragma unroll
        for (int k = 0; k < ED; k += 2) {
            unsigned long long aa = bcast2(a[k]);
            FMA2(m01a, aa, w01[k]); FMA2(m23a, aa, w23[k]);
            unsigned long long ab = bcast2(a[k + 1]);
            FMA2(m01b, ab, w01[k + 1]); FMA2(m23b, ab, w23[k + 1]);
        }
        unsigned long long m01, m23;
        ADD2(m01, m01a, m01b);
        ADD2(m23, m23a, m23b);
        float m0, m1, m2, m3;
        unpack2(m01, m0, m1);
        unpack2(m23, m2, m3);
        float vx = fmaxf(hv.x + m0, 0.f);
        float vy = fmaxf(hv.y + m1, 0.f);
        float vz = fmaxf(hv.z + m2, 0.f);
        float vw = fmaxf(hv.w + m3, 0.f);
        float* ap = aggr + (size_t)dst * HID + lane * 4;
        asm volatile("red.global.add.v4.f32 [%0], {%1, %2, %3, %4};"
                     :: "l"(ap), "f"(vx), "f"(vy), "f"(vz), "f"(vw) : "memory");

        if (!more) break;
        e = en; src = sn; dst = dn;
        e0 = n0; e1 = n1; e2 = n2; e3 = n3; hv = hn;
    }
}

// ---------------- bf16 split + mma helpers ----------------
__device__ __forceinline__ void bsplit(float x, __nv_bfloat16& h, __nv_bfloat16& l) {
    h = __float2bfloat16_rn(x);
    l = __float2bfloat16_rn(x - __bfloat162float(h));
}

__device__ __forceinline__ void mma_bf16(float c[4], const uint32_t a[4], const uint32_t b[2]) {
    asm volatile(
        "mma.sync.aligned.m16n8k16.row.col.f32.bf16.bf16.f32 "
        "{%0,%1,%2,%3}, {%4,%5,%6,%7}, {%8,%9}, {%0,%1,%2,%3};"
        : "+f"(c[0]), "+f"(c[1]), "+f"(c[2]), "+f"(c[3])
        : "r"(a[0]), "r"(a[1]), "r"(a[2]), "r"(a[3]), "r"(b[0]), "r"(b[1]));
}

__device__ __forceinline__ void warp_gemm(
    const __nv_bfloat16* __restrict__ Ah, const __nv_bfloat16* __restrict__ Al,
    const __nv_bfloat16* __restrict__ Wh, const __nv_bfloat16* __restrict__ Wl,
    int nch, int r0, int c0, int grp, int qp, float C[2][8][4])
{
    for (int ch = 0; ch < nch; ch++) {
        const int kc = ch * 16 + qp * 2;
        uint32_t ah[2][4], al[2][4];
        #pragma unroll
        for (int mt = 0; mt < 2; mt++) {
            const __nv_bfloat16* p = Ah + (r0 + mt * 16 + grp) * ASTR + kc;
            const __nv_bfloat16* q = Al + (r0 + mt * 16 + grp) * ASTR + kc;
            ah[mt][0] = *(const uint32_t*)p;
            ah[mt][1] = *(const uint32_t*)(p + 8 * ASTR);
            ah[mt][2] = *(const uint32_t*)(p + 8);
            ah[mt][3] = *(const uint32_t*)(p + 8 * ASTR + 8);
            al[mt][0] = *(const uint32_t*)q;
            al[mt][1] = *(const uint32_t*)(q + 8 * ASTR);
            al[mt][2] = *(const uint32_t*)(q + 8);
            al[mt][3] = *(const uint32_t*)(q + 8 * ASTR + 8);
        }
        #pragma unroll
        for (int nt = 0; nt < 8; nt++) {
            const __nv_bfloat16* p = Wh + (c0 + nt * 8 + grp) * ASTR + kc;
            const __nv_bfloat16* q = Wl + (c0 + nt * 8 + grp) * ASTR + kc;
            uint32_t bh[2] = { *(const uint32_t*)p, *(const uint32_t*)(p + 8) };
            uint32_t bl[2] = { *(const uint32_t*)q, *(const uint32_t*)(q + 8) };
            #pragma unroll
            for (int mt = 0; mt < 2; mt++) {
                mma_bf16(C[mt][nt], ah[mt], bh);
                mma_bf16(C[mt][nt], ah[mt], bl);
                mma_bf16(C[mt][nt], al[mt], bh);
            }
        }
    }
}

// ---------------- fused 2-layer MLP via tensor cores ----------------
template <int KD, int MODE, bool RELU_OUT>
__global__ __launch_bounds__(256) void mlp_mma(
    const float* __restrict__ in, int nrows,
    const float* __restrict__ w1, const float* __restrict__ b1,
    const float* __restrict__ w2, const float* __restrict__ b2,
    const float* __restrict__ xflag,
    float* __restrict__ out, float* __restrict__ out2)
{
    extern __shared__ __nv_bfloat16 smb[];
    __nv_bfloat16* Ah = smb;
    __nv_bfloat16* Al = Ah + 128 * ASTR;
    __nv_bfloat16* Wh = Al + 128 * ASTR;
    __nv_bfloat16* Wl = Wh + 128 * ASTR;

    const int tid = threadIdx.x;
    const int row0 = blockIdx.x * 128;

    for (int i = tid; i < 128 * (KD / 4); i += 256) {
        int r = i / (KD / 4), k4 = (i % (KD / 4)) * 4;
        float4 v = make_float4(0.f, 0.f, 0.f, 0.f);
        int gr = row0 + r;
        if (gr < nrows) v = *(const float4*)(in + (size_t)gr * KD + k4);
        __nv_bfloat16 h0, l0, h1, l1, h2, l2, h3, l3;
        bsplit(v.x, h0, l0); bsplit(v.y, h1, l1);
        bsplit(v.z, h2, l2); bsplit(v.w, h3, l3);
        *(__nv_bfloat162*)&Ah[r * ASTR + k4]     = __halves2bfloat162(h0, h1);
        *(__nv_bfloat162*)&Ah[r * ASTR + k4 + 2] = __halves2bfloat162(h2, h3);
        *(__nv_bfloat162*)&Al[r * ASTR + k4]     = __halves2bfloat162(l0, l1);
        *(__nv_bfloat162*)&Al[r * ASTR + k4 + 2] = __halves2bfloat162(l2, l3);
    }
    for (int i = tid; i < KD * 32; i += 256) {
        int k = i / 32, n = (i % 32) * 4;
        float4 v = *(const float4*)(w1 + (size_t)k * HID + n);
        __nv_bfloat16 h, l;
        bsplit(v.x, h, l); Wh[(n + 0) * ASTR + k] = h; Wl[(n + 0) * ASTR + k] = l;
        bsplit(v.y, h, l); Wh[(n + 1) * ASTR + k] = h; Wl[(n + 1) * ASTR + k] = l;
        bsplit(v.z, h, l); Wh[(n + 2) * ASTR + k] = h; Wl[(n + 2) * ASTR + k] = l;
        bsplit(v.w, h, l); Wh[(n + 3) * ASTR + k] = h; Wl[(n + 3) * ASTR + k] = l;
    }
    __syncthreads();

    const int lane = tid & 31, wid = tid >> 5;
    const int r0 = (wid & 3) * 32, c0 = (wid >> 2) * 64;
    const int grp = lane >> 2, qp = lane & 3;

    float C[2][8][4];
    #pragma unroll
    for (int nt = 0; nt < 8; nt++) {
        float2 bv = *(const float2*)(b1 + c0 + nt * 8 + qp * 2);
        #pragma unroll
        for (int mt = 0; mt < 2; mt++) {
            C[mt][nt][0] = bv.x; C[mt][nt][1] = bv.y;
            C[mt][nt][2] = bv.x; C[mt][nt][3] = bv.y;
        }
    }
    warp_gemm(Ah, Al, Wh, Wl, KD / 16, r0, c0, grp, qp, C);
    __syncthreads();

    #pragma unroll
    for (int mt = 0; mt < 2; mt++) {
        int row = r0 + mt * 16 + grp;
        #pragma unroll
        for (int nt = 0; nt < 8; nt++) {
            int col = c0 + nt * 8 + qp * 2;
            float v0 = fmaxf(C[mt][nt][0], 0.f), v1 = fmaxf(C[mt][nt][1], 0.f);
            float v2 = fmaxf(C[mt][nt][2], 0.f), v3 = fmaxf(C[mt][nt][3], 0.f);
            __nv_bfloat16 ha, la, hb, lb;
            bsplit(v0, ha, la); bsplit(v1, hb, lb);
            *(__nv_bfloat162*)&Ah[row * ASTR + col] = __halves2bfloat162(ha, hb);
            *(__nv_bfloat162*)&Al[row * ASTR + col] = __halves2bfloat162(la, lb);
            bsplit(v2, ha, la); bsplit(v3, hb, lb);
            *(__nv_bfloat162*)&Ah[(row + 8) * ASTR + col] = __halves2bfloat162(ha, hb);
            *(__nv_bfloat162*)&Al[(row + 8) * ASTR + col] = __halves2bfloat162(la, lb);
        }
    }
    for (int i = tid; i < HID * 32; i += 256) {
        int k = i / 32, n = (i % 32) * 4;
        float4 v = *(const float4*)(w2 + (size_t)k * HID + n);
        __nv_bfloat16 h, l;
        bsplit(v.x, h, l); Wh[(n + 0) * ASTR + k] = h; Wl[(n + 0) * ASTR + k] = l;
        bsplit(v.y, h, l); Wh[(n + 1) * ASTR + k] = h; Wl[(n + 1) * ASTR + k] = l;
        bsplit(v.z, h, l); Wh[(n + 2) * ASTR + k] = h; Wl[(n + 2) * ASTR + k] = l;
        bsplit(v.w, h, l); Wh[(n + 3) * ASTR + k] = h; Wl[(n + 3) * ASTR + k] = l;
    }
    __syncthreads();

    #pragma unroll
    for (int nt = 0; nt < 8; nt++) {
        float2 bv = *(const float2*)(b2 + c0 + nt * 8 + qp * 2);
        #pragma unroll
        for (int mt = 0; mt < 2; mt++) {
            C[mt][nt][0] = bv.x; C[mt][nt][1] = bv.y;
            C[mt][nt][2] = bv.x; C[mt][nt][3] = bv.y;
        }
    }
    warp_gemm(Ah, Al, Wh, Wl, HID / 16, r0, c0, grp, qp, C);

    #pragma unroll
    for (int mt = 0; mt < 2; mt++) {
        #pragma unroll
        for (int rh = 0; rh < 2; rh++) {
            int gr = row0 + r0 + mt * 16 + grp + rh * 8;
            if (gr >= nrows) continue;
            if (MODE == 1) { if (xflag[(size_t)gr * IND + (IND - 1)] > 0.5f) continue; }
            if (MODE == 2) { if (!(xflag[(size_t)gr * IND + (IND - 1)] > 0.5f)) continue; }
            #pragma unroll
            for (int nt = 0; nt < 8; nt++) {
                int col = c0 + nt * 8 + qp * 2;
                float v0 = C[mt][nt][rh * 2 + 0], v1 = C[mt][nt][rh * 2 + 1];
                if (RELU_OUT) { v0 = fmaxf(v0, 0.f); v1 = fmaxf(v1, 0.f); }
                float2 o = make_float2(v0, v1);
                *(float2*)(out + (size_t)gr * HID + col) = o;
                if (out2) *(float2*)(out2 + (size_t)gr * HID + col) = o;
            }
        }
    }
}

// ---------------- GraphNorm (+ optional pool, + seed next-layer aggr) ----------------
__global__ __launch_bounds__(512) void gnorm_kernel(
    const float* __restrict__ in, float* __restrict__ out,
    float* __restrict__ out2,
    const float* __restrict__ gw, const float* __restrict__ gb,
    const float* __restrict__ gms, int do_pool)
{
    __shared__ float red[4 * HID];
    __shared__ float stat[HID];
    int g = blockIdx.x;
    int tid = threadIdx.x;
    int c = tid & (HID - 1);
    int sub = tid >> 7;
    int s = d_off[g], e = d_off[g + 1];
    float cnt = fmaxf((float)(e - s), 1.f);

    float sum = 0.f;
    for (int n = s + sub; n < e; n += 4) sum += in[(size_t)n * HID + c];
    red[sub * HID + c] = sum;
    __syncthreads();
    if (sub == 0)
        stat[c] = (red[c] + red[HID + c] + red[2 * HID + c] + red[3 * HID + c]) / cnt * gms[c];
    __syncthreads();
    float mean = stat[c];

    float vs = 0.f;
    for (int n = s + sub; n < e; n += 4) {
        float hc = in[(size_t)n * HID + c] - mean;
        vs += hc * hc;
    }
    red[sub * HID + c] = vs;
    __syncthreads();
    if (sub == 0) {
        float var = (red[c] + red[HID + c] + red[2 * HID + c] + red[3 * HID + c]) / cnt;
        stat[c] = rsqrtf(var + EPSV);
    }
    __syncthreads();
    float w = gw[c] * stat[c];
    float b = gb[c];

    float pool = 0.f;
    for (int n = s + sub; n < e; n += 4) {
        float v = fmaxf((in[(size_t)n * HID + c] - mean) * w + b, 0.f);
        out[(size_t)n * HID + c] = v;
        if (out2) out2[(size_t)n * HID + c] = v;
        pool += v;
    }
    if (do_pool) {
        __syncthreads();
        red[sub * HID + c] = pool;
        __syncthreads();
        if (sub == 0)
            d_g[g * HID + c] = red[c] + red[HID + c] + red[2 * HID + c] + red[3 * HID + c];
    }
}

// ---------------- output head ----------------
__global__ __launch_bounds__(128) void head_kernel(
    const float* __restrict__ fw1, const float* __restrict__ fb1,
    const float* __restrict__ fw2, const float* __restrict__ fb2,
    float* __restrict__ outp)
{
    int i = blockIdx.x;
    int c = threadIdx.x;
    __shared__ float gs[HID];
    __shared__ float red[HID];
    gs[c] = d_g[i * HID + c];
    __syncthreads();
    float acc = fb1[c];
    #pragma unroll 4
    for (int k = 0; k < HID; k++) acc += gs[k] * fw1[k * HID + c];
    red[c] = fmaxf(acc, 0.f) * fw2[c];
    __syncthreads();
    for (int s = 64; s > 0; s >>= 1) {
        if (c < s) red[c] += red[c + s];
        __syncthreads();
    }
    if (c == 0) outp[i] = red[0] + fb2[0];
}

// ---------------- launch ----------------
extern "C" void kernel_launch(void* const* d_in, const int* in_sizes, int n_in,
                              void* d_out, int out_size)
{
    const float* x     = (const float*)d_in[0];
    const int*   ei    = (const int*)d_in[1];
    const float* ea    = (const float*)d_in[2];
    const int*   batch = (const int*)d_in[3];
    const float* lig_w1 = (const float*)d_in[4];
    const float* lig_b1 = (const float*)d_in[5];
    const float* lig_w2 = (const float*)d_in[6];
    const float* lig_b2 = (const float*)d_in[7];
    const float* prot_w1 = (const float*)d_in[8];
    const float* prot_b1 = (const float*)d_in[9];
    const float* prot_w2 = (const float*)d_in[10];
    const float* prot_b2 = (const float*)d_in[11];
    const float* edge_w = (const float*)d_in[12];
    const float* edge_b = (const float*)d_in[13];
    const float* nn_w1 = (const float*)d_in[14];
    const float* nn_b1 = (const float*)d_in[15];
    const float* nn_w2 = (const float*)d_in[16];
    const float* nn_b2 = (const float*)d_in[17];
    const float* gn_w = (const float*)d_in[18];
    const float* gn_b = (const float*)d_in[19];
    const float* gn_ms = (const float*)d_in[20];
    const float* fc_w1 = (const float*)d_in[21];
    const float* fc_b1 = (const float*)d_in[22];
    const float* fc_w2 = (const float*)d_in[23];
    const float* fc_b2 = (const float*)d_in[24];
    float* outp = (float*)d_out;

    float* hptr = nullptr; float* tptr = nullptr;
    cudaGetSymbolAddress((void**)&hptr, d_h);
    cudaGetSymbolAddress((void**)&tptr, d_t);

    const int SMEM_MLP = 4 * 128 * ASTR * (int)sizeof(__nv_bfloat16);  // 135168 B
    cudaFuncSetAttribute(mlp_mma<IND, 1, true>,  cudaFuncAttributeMaxDynamicSharedMemorySize, SMEM_MLP);
    cudaFuncSetAttribute(mlp_mma<IND, 2, true>,  cudaFuncAttributeMaxDynamicSharedMemorySize, SMEM_MLP);
    cudaFuncSetAttribute(mlp_mma<HID, 0, false>, cudaFuncAttributeMaxDynamicSharedMemorySize, SMEM_MLP);

    offsets_kernel<<<1, 256>>>(batch);

    dim3 gB((NN + 127) / 128);  // 391 blocks
    // encoders write h AND seed aggr buffer (t) with h  — msg_red is launch #4 (ncu window)
    mlp_mma<IND, 1, true><<<gB, 256, SMEM_MLP>>>(x, NN, lig_w1, lig_b1, lig_w2, lig_b2, x, hptr, tptr);
    mlp_mma<IND, 2, true><<<gB, 256, SMEM_MLP>>>(x, NN, prot_w1, prot_b1, prot_w2, prot_b2, x, hptr, tptr);

    for (int l = 0; l < 3; l++) {
        msg_red<<<592, 256>>>(ei, ea, edge_w + (size_t)l * ED * HID, edge_b + (size_t)l * HID,
                              hptr, tptr);
        mlp_mma<HID, 0, false><<<gB, 256, SMEM_MLP>>>(
            tptr, NN,
            nn_w1 + (size_t)l * HID * HID, nn_b1 + (size_t)l * HID,
            nn_w2 + (size_t)l * HID * HID, nn_b2 + (size_t)l * HID,
            nullptr, tptr, nullptr);
        gnorm_kernel<<<GG, 512>>>(tptr, hptr, (l < 2) ? tptr : nullptr,
                                  gn_w + (size_t)l * HID, gn_b + (size_t)l * HID,
                                  gn_ms + (size_t)l * HID, (l == 2) ? 1 : 0);
    }

    head_kernel<<<GG, 128>>>(fc_w1, fc_b1, fc_w2, fc_b2, outp);
}

// round 13
// speedup vs baseline: 1.2413x; 1.2413x over previous
#include <cuda_runtime.h>
#include <cuda_bf16.h>
#include <stdint.h>
#include <math.h>

#define NN 50000
#define NE 800000
#define IND 64
#define ED 16
#define HID 128
#define GG 128
#define EPSV 1e-5f
#define ASTR 132   // padded smem row stride (bf16 elems)

// ---------------- scratch (no allocations allowed) ----------------
__device__ float d_h[(size_t)NN * HID];   // node features
__device__ float d_t[(size_t)NN * HID];   // aggr / mlp buffer
__device__ float d_g[GG * HID];           // pooled per-graph
__device__ int   d_off[GG + 1];           // graph segment offsets

// ---------------- graph offsets (batch is sorted int32) ----------------
__global__ void offsets_kernel(const int* __restrict__ batch) {
    int g = blockIdx.x * blockDim.x + threadIdx.x;
    if (g > GG) return;
    int lo = 0, hi = NN;
    while (lo < hi) {
        int mid = (lo + hi) >> 1;
        if (batch[mid] < g) lo = mid + 1; else hi = mid;
    }
    d_off[g] = lo;
}

// ---------------- edge message + vector-red scatter ----------------
// 2 warps per edge; each warp owns a 64-col half (2 cols/lane -> w[16] float2 = 32 regs).
// aggr[dst] += relu(h[src] + ea@W + b)   (aggr pre-seeded with h)
__global__ __launch_bounds__(256, 3) void msg_red(
    const int* __restrict__ ei, const float* __restrict__ ea,
    const float* __restrict__ ew, const float* __restrict__ eb,
    const float* __restrict__ h, float* __restrict__ aggr)
{
    int tid = threadIdx.x, lane = tid & 31, warp = tid >> 5;
    int half = warp & 1;                 // which 64-col half
    int c = half * 64 + lane * 2;        // this lane's 2 absolute columns

    float2 w[ED];
    #pragma unroll
    for (int k = 0; k < ED; k++) w[k] = *(const float2*)(ew + k * HID + c);
    float2 bias = *(const float2*)(eb + c);

    int gpair = (blockIdx.x * 8 + warp) >> 1;   // edge-pair group id
    int npair = gridDim.x * 4;                  // 8 warps/block / 2

    for (int e = gpair; e < NE; e += npair) {
        int src = ei[e];
        int dst = ei[NE + e];
        const float4* ep = (const float4*)(ea + (size_t)e * ED);
        float4 e0 = ep[0], e1 = ep[1], e2 = ep[2], e3 = ep[3];
        float2 hv = *(const float2*)(h + (size_t)src * HID + c);

        float2 ma = bias, mb = make_float2(0.f, 0.f);
        ma.x += e0.x * w[0].x;  ma.y += e0.x * w[0].y;
        mb.x += e0.y * w[1].x;  mb.y += e0.y * w[1].y;
        ma.x += e0.z * w[2].x;  ma.y += e0.z * w[2].y;
        mb.x += e0.w * w[3].x;  mb.y += e0.w * w[3].y;
        ma.x += e1.x * w[4].x;  ma.y += e1.x * w[4].y;
        mb.x += e1.y * w[5].x;  mb.y += e1.y * w[5].y;
        ma.x += e1.z * w[6].x;  ma.y += e1.z * w[6].y;
        mb.x += e1.w * w[7].x;  mb.y += e1.w * w[7].y;
        ma.x += e2.x * w[8].x;  ma.y += e2.x * w[8].y;
        mb.x += e2.y * w[9].x;  mb.y += e2.y * w[9].y;
        ma.x += e2.z * w[10].x; ma.y += e2.z * w[10].y;
        mb.x += e2.w * w[11].x; mb.y += e2.w * w[11].y;
        ma.x += e3.x * w[12].x; ma.y += e3.x * w[12].y;
        mb.x += e3.y * w[13].x; mb.y += e3.y * w[13].y;
        ma.x += e3.z * w[14].x; ma.y += e3.z * w[14].y;
        mb.x += e3.w * w[15].x; mb.y += e3.w * w[15].y;

        float vx = fmaxf(hv.x + ma.x + mb.x, 0.f);
        float vy = fmaxf(hv.y + ma.y + mb.y, 0.f);
        float* ap = aggr + (size_t)dst * HID + c;
        asm volatile("red.global.add.v2.f32 [%0], {%1, %2};"
                     :: "l"(ap), "f"(vx), "f"(vy) : "memory");
    }
}

// ---------------- bf16 split + mma helpers ----------------
__device__ __forceinline__ void bsplit(float x, __nv_bfloat16& h, __nv_bfloat16& l) {
    h = __float2bfloat16_rn(x);
    l = __float2bfloat16_rn(x - __bfloat162float(h));
}

__device__ __forceinline__ void mma_bf16(float c[4], const uint32_t a[4], const uint32_t b[2]) {
    asm volatile(
        "mma.sync.aligned.m16n8k16.row.col.f32.bf16.bf16.f32 "
        "{%0,%1,%2,%3}, {%4,%5,%6,%7}, {%8,%9}, {%0,%1,%2,%3};"
        : "+f"(c[0]), "+f"(c[1]), "+f"(c[2]), "+f"(c[3])
        : "r"(a[0]), "r"(a[1]), "r"(a[2]), "r"(a[3]), "r"(b[0]), "r"(b[1]));
}

__device__ __forceinline__ void warp_gemm(
    const __nv_bfloat16* __restrict__ Ah, const __nv_bfloat16* __restrict__ Al,
    const __nv_bfloat16* __restrict__ Wh, const __nv_bfloat16* __restrict__ Wl,
    int nch, int r0, int c0, int grp, int qp, float C[2][8][4])
{
    for (int ch = 0; ch < nch; ch++) {
        const int kc = ch * 16 + qp * 2;
        uint32_t ah[2][4], al[2][4];
        #pragma unroll
        for (int mt = 0; mt < 2; mt++) {
            const __nv_bfloat16* p = Ah + (r0 + mt * 16 + grp) * ASTR + kc;
            const __nv_bfloat16* q = Al + (r0 + mt * 16 + grp) * ASTR + kc;
            ah[mt][0] = *(const uint32_t*)p;
            ah[mt][1] = *(const uint32_t*)(p + 8 * ASTR);
            ah[mt][2] = *(const uint32_t*)(p + 8);
            ah[mt][3] = *(const uint32_t*)(p + 8 * ASTR + 8);
            al[mt][0] = *(const uint32_t*)q;
            al[mt][1] = *(const uint32_t*)(q + 8 * ASTR);
            al[mt][2] = *(const uint32_t*)(q + 8);
            al[mt][3] = *(const uint32_t*)(q + 8 * ASTR + 8);
        }
        #pragma unroll
        for (int nt = 0; nt < 8; nt++) {
            const __nv_bfloat16* p = Wh + (c0 + nt * 8 + grp) * ASTR + kc;
            const __nv_bfloat16* q = Wl + (c0 + nt * 8 + grp) * ASTR + kc;
            uint32_t bh[2] = { *(const uint32_t*)p, *(const uint32_t*)(p + 8) };
            uint32_t bl[2] = { *(const uint32_t*)q, *(const uint32_t*)(q + 8) };
            #pragma unroll
            for (int mt = 0; mt < 2; mt++) {
                mma_bf16(C[mt][nt], ah[mt], bh);
                mma_bf16(C[mt][nt], ah[mt], bl);
                mma_bf16(C[mt][nt], al[mt], bh);
            }
        }
    }
}

// ---------------- fused 2-layer MLP via tensor cores ----------------
template <int KD, int MODE, bool RELU_OUT>
__global__ __launch_bounds__(256) void mlp_mma(
    const float* __restrict__ in, int nrows,
    const float* __restrict__ w1, const float* __restrict__ b1,
    const float* __restrict__ w2, const float* __restrict__ b2,
    const float* __restrict__ xflag,
    float* __restrict__ out, float* __restrict__ out2)
{
    extern __shared__ __nv_bfloat16 smb[];
    __nv_bfloat16* Ah = smb;
    __nv_bfloat16* Al = Ah + 128 * ASTR;
    __nv_bfloat16* Wh = Al + 128 * ASTR;
    __nv_bfloat16* Wl = Wh + 128 * ASTR;

    const int tid = threadIdx.x;
    const int row0 = blockIdx.x * 128;

    for (int i = tid; i < 128 * (KD / 4); i += 256) {
        int r = i / (KD / 4), k4 = (i % (KD / 4)) * 4;
        float4 v = make_float4(0.f, 0.f, 0.f, 0.f);
        int gr = row0 + r;
        if (gr < nrows) v = *(const float4*)(in + (size_t)gr * KD + k4);
        __nv_bfloat16 h0, l0, h1, l1, h2, l2, h3, l3;
        bsplit(v.x, h0, l0); bsplit(v.y, h1, l1);
        bsplit(v.z, h2, l2); bsplit(v.w, h3, l3);
        *(__nv_bfloat162*)&Ah[r * ASTR + k4]     = __halves2bfloat162(h0, h1);
        *(__nv_bfloat162*)&Ah[r * ASTR + k4 + 2] = __halves2bfloat162(h2, h3);
        *(__nv_bfloat162*)&Al[r * ASTR + k4]     = __halves2bfloat162(l0, l1);
        *(__nv_bfloat162*)&Al[r * ASTR + k4 + 2] = __halves2bfloat162(l2, l3);
    }
    for (int i = tid; i < KD * 32; i += 256) {
        int k = i / 32, n = (i % 32) * 4;
        float4 v = *(const float4*)(w1 + (size_t)k * HID + n);
        __nv_bfloat16 h, l;
        bsplit(v.x, h, l); Wh[(n + 0) * ASTR + k] = h; Wl[(n + 0) * ASTR + k] = l;
        bsplit(v.y, h, l); Wh[(n + 1) * ASTR + k] = h; Wl[(n + 1) * ASTR + k] = l;
        bsplit(v.z, h, l); Wh[(n + 2) * ASTR + k] = h; Wl[(n + 2) * ASTR + k] = l;
        bsplit(v.w, h, l); Wh[(n + 3) * ASTR + k] = h; Wl[(n + 3) * ASTR + k] = l;
    }
    __syncthreads();

    const int lane = tid & 31, wid = tid >> 5;
    const int r0 = (wid & 3) * 32, c0 = (wid >> 2) * 64;
    const int grp = lane >> 2, qp = lane & 3;

    float C[2][8][4];
    #pragma unroll
    for (int nt = 0; nt < 8; nt++) {
        float2 bv = *(const float2*)(b1 + c0 + nt * 8 + qp * 2);
        #pragma unroll
        for (int mt = 0; mt < 2; mt++) {
            C[mt][nt][0] = bv.x; C[mt][nt][1] = bv.y;
            C[mt][nt][2] = bv.x; C[mt][nt][3] = bv.y;
        }
    }
    warp_gemm(Ah, Al, Wh, Wl, KD / 16, r0, c0, grp, qp, C);
    __syncthreads();

    #pragma unroll
    for (int mt = 0; mt < 2; mt++) {
        int row = r0 + mt * 16 + grp;
        #pragma unroll
        for (int nt = 0; nt < 8; nt++) {
            int col = c0 + nt * 8 + qp * 2;
            float v0 = fmaxf(C[mt][nt][0], 0.f), v1 = fmaxf(C[mt][nt][1], 0.f);
            float v2 = fmaxf(C[mt][nt][2], 0.f), v3 = fmaxf(C[mt][nt][3], 0.f);
            __nv_bfloat16 ha, la, hb, lb;
            bsplit(v0, ha, la); bsplit(v1, hb, lb);
            *(__nv_bfloat162*)&Ah[row * ASTR + col] = __halves2bfloat162(ha, hb);
            *(__nv_bfloat162*)&Al[row * ASTR + col] = __halves2bfloat162(la, lb);
            bsplit(v2, ha, la); bsplit(v3, hb, lb);
            *(__nv_bfloat162*)&Ah[(row + 8) * ASTR + col] = __halves2bfloat162(ha, hb);
            *(__nv_bfloat162*)&Al[(row + 8) * ASTR + col] = __halves2bfloat162(la, lb);
        }
    }
    for (int i = tid; i < HID * 32; i += 256) {
        int k = i / 32, n = (i % 32) * 4;
        float4 v = *(const float4*)(w2 + (size_t)k * HID + n);
        __nv_bfloat16 h, l;
        bsplit(v.x, h, l); Wh[(n + 0) * ASTR + k] = h; Wl[(n + 0) * ASTR + k] = l;
        bsplit(v.y, h, l); Wh[(n + 1) * ASTR + k] = h; Wl[(n + 1) * ASTR + k] = l;
        bsplit(v.z, h, l); Wh[(n + 2) * ASTR + k] = h; Wl[(n + 2) * ASTR + k] = l;
        bsplit(v.w, h, l); Wh[(n + 3) * ASTR + k] = h; Wl[(n + 3) * ASTR + k] = l;
    }
    __syncthreads();

    #pragma unroll
    for (int nt = 0; nt < 8; nt++) {
        float2 bv = *(const float2*)(b2 + c0 + nt * 8 + qp * 2);
        #pragma unroll
        for (int mt = 0; mt < 2; mt++) {
            C[mt][nt][0] = bv.x; C[mt][nt][1] = bv.y;
            C[mt][nt][2] = bv.x; C[mt][nt][3] = bv.y;
        }
    }
    warp_gemm(Ah, Al, Wh, Wl, HID / 16, r0, c0, grp, qp, C);

    #pragma unroll
    for (int mt = 0; mt < 2; mt++) {
        #pragma unroll
        for (int rh = 0; rh < 2; rh++) {
            int gr = row0 + r0 + mt * 16 + grp + rh * 8;
            if (gr >= nrows) continue;
            if (MODE == 1) { if (xflag[(size_t)gr * IND + (IND - 1)] > 0.5f) continue; }
            if (MODE == 2) { if (!(xflag[(size_t)gr * IND + (IND - 1)] > 0.5f)) continue; }
            #pragma unroll
            for (int nt = 0; nt < 8; nt++) {
                int col = c0 + nt * 8 + qp * 2;
                float v0 = C[mt][nt][rh * 2 + 0], v1 = C[mt][nt][rh * 2 + 1];
                if (RELU_OUT) { v0 = fmaxf(v0, 0.f); v1 = fmaxf(v1, 0.f); }
                float2 o = make_float2(v0, v1);
                *(float2*)(out + (size_t)gr * HID + col) = o;
                if (out2) *(float2*)(out2 + (size_t)gr * HID + col) = o;
            }
        }
    }
}

// ---------------- GraphNorm (+ optional pool, + seed next-layer aggr) ----------------
__global__ __launch_bounds__(512) void gnorm_kernel(
    const float* __restrict__ in, float* __restrict__ out,
    float* __restrict__ out2,
    const float* __restrict__ gw, const float* __restrict__ gb,
    const float* __restrict__ gms, int do_pool)
{
    __shared__ float red[4 * HID];
    __shared__ float stat[HID];
    int g = blockIdx.x;
    int tid = threadIdx.x;
    int c = tid & (HID - 1);
    int sub = tid >> 7;
    int s = d_off[g], e = d_off[g + 1];
    float cnt = fmaxf((float)(e - s), 1.f);

    float sum = 0.f;
    for (int n = s + sub; n < e; n += 4) sum += in[(size_t)n * HID + c];
    red[sub * HID + c] = sum;
    __syncthreads();
    if (sub == 0)
        stat[c] = (red[c] + red[HID + c] + red[2 * HID + c] + red[3 * HID + c]) / cnt * gms[c];
    __syncthreads();
    float mean = stat[c];

    float vs = 0.f;
    for (int n = s + sub; n < e; n += 4) {
        float hc = in[(size_t)n * HID + c] - mean;
        vs += hc * hc;
    }
    red[sub * HID + c] = vs;
    __syncthreads();
    if (sub == 0) {
        float var = (red[c] + red[HID + c] + red[2 * HID + c] + red[3 * HID + c]) / cnt;
        stat[c] = rsqrtf(var + EPSV);
    }
    __syncthreads();
    float w = gw[c] * stat[c];
    float b = gb[c];

    float pool = 0.f;
    for (int n = s + sub; n < e; n += 4) {
        float v = fmaxf((in[(size_t)n * HID + c] - mean) * w + b, 0.f);
        out[(size_t)n * HID + c] = v;
        if (out2) out2[(size_t)n * HID + c] = v;
        pool += v;
    }
    if (do_pool) {
        __syncthreads();
        red[sub * HID + c] = pool;
        __syncthreads();
        if (sub == 0)
            d_g[g * HID + c] = red[c] + red[HID + c] + red[2 * HID + c] + red[3 * HID + c];
    }
}

// ---------------- output head ----------------
__global__ __launch_bounds__(128) void head_kernel(
    const float* __restrict__ fw1, const float* __restrict__ fb1,
    const float* __restrict__ fw2, const float* __restrict__ fb2,
    float* __restrict__ outp)
{
    int i = blockIdx.x;
    int c = threadIdx.x;
    __shared__ float gs[HID];
    __shared__ float red[HID];
    gs[c] = d_g[i * HID + c];
    __syncthreads();
    float acc = fb1[c];
    #pragma unroll 4
    for (int k = 0; k < HID; k++) acc += gs[k] * fw1[k * HID + c];
    red[c] = fmaxf(acc, 0.f) * fw2[c];
    __syncthreads();
    for (int s = 64; s > 0; s >>= 1) {
        if (c < s) red[c] += red[c + s];
        __syncthreads();
    }
    if (c == 0) outp[i] = red[0] + fb2[0];
}

// ---------------- launch ----------------
extern "C" void kernel_launch(void* const* d_in, const int* in_sizes, int n_in,
                              void* d_out, int out_size)
{
    const float* x     = (const float*)d_in[0];
    const int*   ei    = (const int*)d_in[1];
    const float* ea    = (const float*)d_in[2];
    const int*   batch = (const int*)d_in[3];
    const float* lig_w1 = (const float*)d_in[4];
    const float* lig_b1 = (const float*)d_in[5];
    const float* lig_w2 = (const float*)d_in[6];
    const float* lig_b2 = (const float*)d_in[7];
    const float* prot_w1 = (const float*)d_in[8];
    const float* prot_b1 = (const float*)d_in[9];
    const float* prot_w2 = (const float*)d_in[10];
    const float* prot_b2 = (const float*)d_in[11];
    const float* edge_w = (const float*)d_in[12];
    const float* edge_b = (const float*)d_in[13];
    const float* nn_w1 = (const float*)d_in[14];
    const float* nn_b1 = (const float*)d_in[15];
    const float* nn_w2 = (const float*)d_in[16];
    const float* nn_b2 = (const float*)d_in[17];
    const float* gn_w = (const float*)d_in[18];
    const float* gn_b = (const float*)d_in[19];
    const float* gn_ms = (const float*)d_in[20];
    const float* fc_w1 = (const float*)d_in[21];
    const float* fc_b1 = (const float*)d_in[22];
    const float* fc_w2 = (const float*)d_in[23];
    const float* fc_b2 = (const float*)d_in[24];
    float* outp = (float*)d_out;

    float* hptr = nullptr; float* tptr = nullptr;
    cudaGetSymbolAddress((void**)&hptr, d_h);
    cudaGetSymbolAddress((void**)&tptr, d_t);

    const int SMEM_MLP = 4 * 128 * ASTR * (int)sizeof(__nv_bfloat16);  // 135168 B
    cudaFuncSetAttribute(mlp_mma<IND, 1, true>,  cudaFuncAttributeMaxDynamicSharedMemorySize, SMEM_MLP);
    cudaFuncSetAttribute(mlp_mma<IND, 2, true>,  cudaFuncAttributeMaxDynamicSharedMemorySize, SMEM_MLP);
    cudaFuncSetAttribute(mlp_mma<HID, 0, false>, cudaFuncAttributeMaxDynamicSharedMemorySize, SMEM_MLP);

    offsets_kernel<<<1, 256>>>(batch);

    dim3 gB((NN + 127) / 128);  // 391 blocks
    // encoders write h AND seed aggr buffer (t) with h  — msg_red is launch #4 (ncu window)
    mlp_mma<IND, 1, true><<<gB, 256, SMEM_MLP>>>(x, NN, lig_w1, lig_b1, lig_w2, lig_b2, x, hptr, tptr);
    mlp_mma<IND, 2, true><<<gB, 256, SMEM_MLP>>>(x, NN, prot_w1, prot_b1, prot_w2, prot_b2, x, hptr, tptr);

    for (int l = 0; l < 3; l++) {
        msg_red<<<3200, 256>>>(ei, ea, edge_w + (size_t)l * ED * HID, edge_b + (size_t)l * HID,
                               hptr, tptr);
        mlp_mma<HID, 0, false><<<gB, 256, SMEM_MLP>>>(
            tptr, NN,
            nn_w1 + (size_t)l * HID * HID, nn_b1 + (size_t)l * HID,
            nn_w2 + (size_t)l * HID * HID, nn_b2 + (size_t)l * HID,
            nullptr, tptr, nullptr);
        gnorm_kernel<<<GG, 512>>>(tptr, hptr, (l < 2) ? tptr : nullptr,
                                  gn_w + (size_t)l * HID, gn_b + (size_t)l * HID,
                                  gn_ms + (size_t)l * HID, (l == 2) ? 1 : 0);
    }

    head_kernel<<<GG, 128>>>(fc_w1, fc_b1, fc_w2, fc_b2, outp);
}

// round 14
// speedup vs baseline: 1.5795x; 1.2724x over previous
#include <cuda_runtime.h>
#include <cuda_bf16.h>
#include <stdint.h>
#include <math.h>

#define NN 50000
#define NE 800000
#define IND 64
#define ED 16
#define HID 128
#define GG 128
#define EPSV 1e-5f
#define ASTR 132   // padded smem row stride for 128-wide tiles (bf16 elems)
#define EASTR 20   // padded smem row stride for 16-wide edge tiles (bf16 elems)
#define ESTR 132   // E fp32 row stride (floats)

// ---------------- scratch (no allocations allowed) ----------------
__device__ float d_h[(size_t)NN * HID];   // node features
__device__ float d_t[(size_t)NN * HID];   // aggr / mlp buffer
__device__ float d_g[GG * HID];           // pooled per-graph
__device__ int   d_off[GG + 1];           // graph segment offsets

// ---------------- graph offsets (batch is sorted int32) ----------------
__global__ void offsets_kernel(const int* __restrict__ batch) {
    int g = blockIdx.x * blockDim.x + threadIdx.x;
    if (g > GG) return;
    int lo = 0, hi = NN;
    while (lo < hi) {
        int mid = (lo + hi) >> 1;
        if (batch[mid] < g) lo = mid + 1; else hi = mid;
    }
    d_off[g] = lo;
}

// ---------------- bf16 split + mma helpers ----------------
__device__ __forceinline__ void bsplit(float x, __nv_bfloat16& h, __nv_bfloat16& l) {
    h = __float2bfloat16_rn(x);
    l = __float2bfloat16_rn(x - __bfloat162float(h));
}

__device__ __forceinline__ void mma_bf16(float c[4], const uint32_t a[4], const uint32_t b[2]) {
    asm volatile(
        "mma.sync.aligned.m16n8k16.row.col.f32.bf16.bf16.f32 "
        "{%0,%1,%2,%3}, {%4,%5,%6,%7}, {%8,%9}, {%0,%1,%2,%3};"
        : "+f"(c[0]), "+f"(c[1]), "+f"(c[2]), "+f"(c[3])
        : "r"(a[0]), "r"(a[1]), "r"(a[2]), "r"(a[3]), "r"(b[0]), "r"(b[1]));
}

// warp computes 32x64 of C += A[32 x 16*nch] * W^T, bf16x3 compensated.
// A: row-major [row][k] stride astr (hi/lo). W: transposed [n][k] stride astr (hi/lo).
__device__ __forceinline__ void warp_gemm(
    const __nv_bfloat16* __restrict__ Ah, const __nv_bfloat16* __restrict__ Al,
    const __nv_bfloat16* __restrict__ Wh, const __nv_bfloat16* __restrict__ Wl,
    int nch, int astr, int r0, int c0, int grp, int qp, float C[2][8][4])
{
    for (int ch = 0; ch < nch; ch++) {
        const int kc = ch * 16 + qp * 2;
        uint32_t ah[2][4], al[2][4];
        #pragma unroll
        for (int mt = 0; mt < 2; mt++) {
            const __nv_bfloat16* p = Ah + (r0 + mt * 16 + grp) * astr + kc;
            const __nv_bfloat16* q = Al + (r0 + mt * 16 + grp) * astr + kc;
            ah[mt][0] = *(const uint32_t*)p;
            ah[mt][1] = *(const uint32_t*)(p + 8 * astr);
            ah[mt][2] = *(const uint32_t*)(p + 8);
            ah[mt][3] = *(const uint32_t*)(p + 8 * astr + 8);
            al[mt][0] = *(const uint32_t*)q;
            al[mt][1] = *(const uint32_t*)(q + 8 * astr);
            al[mt][2] = *(const uint32_t*)(q + 8);
            al[mt][3] = *(const uint32_t*)(q + 8 * astr + 8);
        }
        #pragma unroll
        for (int nt = 0; nt < 8; nt++) {
            const __nv_bfloat16* p = Wh + (c0 + nt * 8 + grp) * astr + kc;
            const __nv_bfloat16* q = Wl + (c0 + nt * 8 + grp) * astr + kc;
            uint32_t bh[2] = { *(const uint32_t*)p, *(const uint32_t*)(p + 8) };
            uint32_t bl[2] = { *(const uint32_t*)q, *(const uint32_t*)(q + 8) };
            #pragma unroll
            for (int mt = 0; mt < 2; mt++) {
                mma_bf16(C[mt][nt], ah[mt], bh);
                mma_bf16(C[mt][nt], ah[mt], bl);
                mma_bf16(C[mt][nt], al[mt], bh);
            }
        }
    }
}

// ---------------- edge message via tensor cores ----------------
// Tile of 128 edges per CTA: E = ea_tile @ W + b (mma), then
// aggr[dst] += relu(h[src] + E_row)  via red.v4  (aggr pre-seeded with h).
__global__ __launch_bounds__(256) void msg_mma(
    const int* __restrict__ ei, const float* __restrict__ ea,
    const float* __restrict__ ew, const float* __restrict__ eb,
    const float* __restrict__ h, float* __restrict__ aggr)
{
    extern __shared__ char smraw[];
    __nv_bfloat16* Ah = (__nv_bfloat16*)smraw;         // ea tile hi  [128][EASTR]
    __nv_bfloat16* Al = Ah + 128 * EASTR;              // ea tile lo
    __nv_bfloat16* Wh = Al + 128 * EASTR;              // W^T hi      [128 n][EASTR k]
    __nv_bfloat16* Wl = Wh + 128 * EASTR;              // W^T lo
    float* E = (float*)(Wl + 128 * EASTR);             // E fp32      [128][ESTR]

    const int tid = threadIdx.x;
    const int ebase = blockIdx.x * 128;

    // load ea tile [128][16] -> bf16 hi/lo (each thread: 2 float4)
    for (int i = tid; i < 128 * 4; i += 256) {
        int r = i >> 2, k4 = (i & 3) * 4;
        float4 v = *(const float4*)(ea + (size_t)(ebase + r) * ED + k4);
        __nv_bfloat16 h0, l0, h1, l1, h2, l2, h3, l3;
        bsplit(v.x, h0, l0); bsplit(v.y, h1, l1);
        bsplit(v.z, h2, l2); bsplit(v.w, h3, l3);
        *(__nv_bfloat162*)&Ah[r * EASTR + k4]     = __halves2bfloat162(h0, h1);
        *(__nv_bfloat162*)&Ah[r * EASTR + k4 + 2] = __halves2bfloat162(h2, h3);
        *(__nv_bfloat162*)&Al[r * EASTR + k4]     = __halves2bfloat162(l0, l1);
        *(__nv_bfloat162*)&Al[r * EASTR + k4 + 2] = __halves2bfloat162(l2, l3);
    }
    // load W [16][128] transposed -> Wt[n][k] hi/lo
    for (int i = tid; i < 16 * 32; i += 256) {
        int k = i >> 5, n = (i & 31) * 4;
        float4 v = *(const float4*)(ew + (size_t)k * HID + n);
        __nv_bfloat16 hh, ll;
        bsplit(v.x, hh, ll); Wh[(n + 0) * EASTR + k] = hh; Wl[(n + 0) * EASTR + k] = ll;
        bsplit(v.y, hh, ll); Wh[(n + 1) * EASTR + k] = hh; Wl[(n + 1) * EASTR + k] = ll;
        bsplit(v.z, hh, ll); Wh[(n + 2) * EASTR + k] = hh; Wl[(n + 2) * EASTR + k] = ll;
        bsplit(v.w, hh, ll); Wh[(n + 3) * EASTR + k] = hh; Wl[(n + 3) * EASTR + k] = ll;
    }
    __syncthreads();

    const int lane = tid & 31, wid = tid >> 5;
    const int r0 = (wid & 3) * 32, c0 = (wid >> 2) * 64;
    const int grp = lane >> 2, qp = lane & 3;

    float C[2][8][4];
    #pragma unroll
    for (int nt = 0; nt < 8; nt++) {
        float2 bv = *(const float2*)(eb + c0 + nt * 8 + qp * 2);
        #pragma unroll
        for (int mt = 0; mt < 2; mt++) {
            C[mt][nt][0] = bv.x; C[mt][nt][1] = bv.y;
            C[mt][nt][2] = bv.x; C[mt][nt][3] = bv.y;
        }
    }
    warp_gemm(Ah, Al, Wh, Wl, 1, EASTR, r0, c0, grp, qp, C);

    // spill E fragments to fp32 smem
    #pragma unroll
    for (int mt = 0; mt < 2; mt++) {
        int row = r0 + mt * 16 + grp;
        #pragma unroll
        for (int nt = 0; nt < 8; nt++) {
            int col = c0 + nt * 8 + qp * 2;
            *(float2*)&E[row * ESTR + col]       = make_float2(C[mt][nt][0], C[mt][nt][1]);
            *(float2*)&E[(row + 8) * ESTR + col] = make_float2(C[mt][nt][2], C[mt][nt][3]);
        }
    }
    __syncthreads();

    // epilogue: warp w owns edges [w*16, w*16+16)
    const float4* h4 = (const float4*)h;
    int rbase = wid * 16;
    #pragma unroll 4
    for (int i = 0; i < 16; i++) {
        int e = ebase + rbase + i;
        int src = ei[e];
        int dst = ei[NE + e];
        float4 ev = *(const float4*)&E[(rbase + i) * ESTR + lane * 4];
        float4 hv = h4[(size_t)src * 32 + lane];
        float vx = fmaxf(hv.x + ev.x, 0.f);
        float vy = fmaxf(hv.y + ev.y, 0.f);
        float vz = fmaxf(hv.z + ev.z, 0.f);
        float vw = fmaxf(hv.w + ev.w, 0.f);
        float* ap = aggr + (size_t)dst * HID + lane * 4;
        asm volatile("red.global.add.v4.f32 [%0], {%1, %2, %3, %4};"
                     :: "l"(ap), "f"(vx), "f"(vy), "f"(vz), "f"(vw) : "memory");
    }
}

// ---------------- fused 2-layer MLP via tensor cores ----------------
template <int KD, int MODE, bool RELU_OUT>
__global__ __launch_bounds__(256) void mlp_mma(
    const float* __restrict__ in, int nrows,
    const float* __restrict__ w1, const float* __restrict__ b1,
    const float* __restrict__ w2, const float* __restrict__ b2,
    const float* __restrict__ xflag,
    float* __restrict__ out, float* __restrict__ out2)
{
    extern __shared__ __nv_bfloat16 smb[];
    __nv_bfloat16* Ah = smb;
    __nv_bfloat16* Al = Ah + 128 * ASTR;
    __nv_bfloat16* Wh = Al + 128 * ASTR;
    __nv_bfloat16* Wl = Wh + 128 * ASTR;

    const int tid = threadIdx.x;
    const int row0 = blockIdx.x * 128;

    for (int i = tid; i < 128 * (KD / 4); i += 256) {
        int r = i / (KD / 4), k4 = (i % (KD / 4)) * 4;
        float4 v = make_float4(0.f, 0.f, 0.f, 0.f);
        int gr = row0 + r;
        if (gr < nrows) v = *(const float4*)(in + (size_t)gr * KD + k4);
        __nv_bfloat16 h0, l0, h1, l1, h2, l2, h3, l3;
        bsplit(v.x, h0, l0); bsplit(v.y, h1, l1);
        bsplit(v.z, h2, l2); bsplit(v.w, h3, l3);
        *(__nv_bfloat162*)&Ah[r * ASTR + k4]     = __halves2bfloat162(h0, h1);
        *(__nv_bfloat162*)&Ah[r * ASTR + k4 + 2] = __halves2bfloat162(h2, h3);
        *(__nv_bfloat162*)&Al[r * ASTR + k4]     = __halves2bfloat162(l0, l1);
        *(__nv_bfloat162*)&Al[r * ASTR + k4 + 2] = __halves2bfloat162(l2, l3);
    }
    for (int i = tid; i < KD * 32; i += 256) {
        int k = i / 32, n = (i % 32) * 4;
        float4 v = *(const float4*)(w1 + (size_t)k * HID + n);
        __nv_bfloat16 h, l;
        bsplit(v.x, h, l); Wh[(n + 0) * ASTR + k] = h; Wl[(n + 0) * ASTR + k] = l;
        bsplit(v.y, h, l); Wh[(n + 1) * ASTR + k] = h; Wl[(n + 1) * ASTR + k] = l;
        bsplit(v.z, h, l); Wh[(n + 2) * ASTR + k] = h; Wl[(n + 2) * ASTR + k] = l;
        bsplit(v.w, h, l); Wh[(n + 3) * ASTR + k] = h; Wl[(n + 3) * ASTR + k] = l;
    }
    __syncthreads();

    const int lane = tid & 31, wid = tid >> 5;
    const int r0 = (wid & 3) * 32, c0 = (wid >> 2) * 64;
    const int grp = lane >> 2, qp = lane & 3;

    float C[2][8][4];
    #pragma unroll
    for (int nt = 0; nt < 8; nt++) {
        float2 bv = *(const float2*)(b1 + c0 + nt * 8 + qp * 2);
        #pragma unroll
        for (int mt = 0; mt < 2; mt++) {
            C[mt][nt][0] = bv.x; C[mt][nt][1] = bv.y;
            C[mt][nt][2] = bv.x; C[mt][nt][3] = bv.y;
        }
    }
    warp_gemm(Ah, Al, Wh, Wl, KD / 16, ASTR, r0, c0, grp, qp, C);
    __syncthreads();

    #pragma unroll
    for (int mt = 0; mt < 2; mt++) {
        int row = r0 + mt * 16 + grp;
        #pragma unroll
        for (int nt = 0; nt < 8; nt++) {
            int col = c0 + nt * 8 + qp * 2;
            float v0 = fmaxf(C[mt][nt][0], 0.f), v1 = fmaxf(C[mt][nt][1], 0.f);
            float v2 = fmaxf(C[mt][nt][2], 0.f), v3 = fmaxf(C[mt][nt][3], 0.f);
            __nv_bfloat16 ha, la, hb, lb;
            bsplit(v0, ha, la); bsplit(v1, hb, lb);
            *(__nv_bfloat162*)&Ah[row * ASTR + col] = __halves2bfloat162(ha, hb);
            *(__nv_bfloat162*)&Al[row * ASTR + col] = __halves2bfloat162(la, lb);
            bsplit(v2, ha, la); bsplit(v3, hb, lb);
            *(__nv_bfloat162*)&Ah[(row + 8) * ASTR + col] = __halves2bfloat162(ha, hb);
            *(__nv_bfloat162*)&Al[(row + 8) * ASTR + col] = __halves2bfloat162(la, lb);
        }
    }
    for (int i = tid; i < HID * 32; i += 256) {
        int k = i / 32, n = (i % 32) * 4;
        float4 v = *(const float4*)(w2 + (size_t)k * HID + n);
        __nv_bfloat16 h, l;
        bsplit(v.x, h, l); Wh[(n + 0) * ASTR + k] = h; Wl[(n + 0) * ASTR + k] = l;
        bsplit(v.y, h, l); Wh[(n + 1) * ASTR + k] = h; Wl[(n + 1) * ASTR + k] = l;
        bsplit(v.z, h, l); Wh[(n + 2) * ASTR + k] = h; Wl[(n + 2) * ASTR + k] = l;
        bsplit(v.w, h, l); Wh[(n + 3) * ASTR + k] = h; Wl[(n + 3) * ASTR + k] = l;
    }
    __syncthreads();

    #pragma unroll
    for (int nt = 0; nt < 8; nt++) {
        float2 bv = *(const float2*)(b2 + c0 + nt * 8 + qp * 2);
        #pragma unroll
        for (int mt = 0; mt < 2; mt++) {
            C[mt][nt][0] = bv.x; C[mt][nt][1] = bv.y;
            C[mt][nt][2] = bv.x; C[mt][nt][3] = bv.y;
        }
    }
    warp_gemm(Ah, Al, Wh, Wl, HID / 16, ASTR, r0, c0, grp, qp, C);

    #pragma unroll
    for (int mt = 0; mt < 2; mt++) {
        #pragma unroll
        for (int rh = 0; rh < 2; rh++) {
            int gr = row0 + r0 + mt * 16 + grp + rh * 8;
            if (gr >= nrows) continue;
            if (MODE == 1) { if (xflag[(size_t)gr * IND + (IND - 1)] > 0.5f) continue; }
            if (MODE == 2) { if (!(xflag[(size_t)gr * IND + (IND - 1)] > 0.5f)) continue; }
            #pragma unroll
            for (int nt = 0; nt < 8; nt++) {
                int col = c0 + nt * 8 + qp * 2;
                float v0 = C[mt][nt][rh * 2 + 0], v1 = C[mt][nt][rh * 2 + 1];
                if (RELU_OUT) { v0 = fmaxf(v0, 0.f); v1 = fmaxf(v1, 0.f); }
                float2 o = make_float2(v0, v1);
                *(float2*)(out + (size_t)gr * HID + col) = o;
                if (out2) *(float2*)(out2 + (size_t)gr * HID + col) = o;
            }
        }
    }
}

// ---------------- GraphNorm (+ optional pool, + seed next-layer aggr) ----------------
__global__ __launch_bounds__(512) void gnorm_kernel(
    const float* __restrict__ in, float* __restrict__ out,
    float* __restrict__ out2,
    const float* __restrict__ gw, const float* __restrict__ gb,
    const float* __restrict__ gms, int do_pool)
{
    __shared__ float red[4 * HID];
    __shared__ float stat[HID];
    int g = blockIdx.x;
    int tid = threadIdx.x;
    int c = tid & (HID - 1);
    int sub = tid >> 7;
    int s = d_off[g], e = d_off[g + 1];
    float cnt = fmaxf((float)(e - s), 1.f);

    float sum = 0.f;
    for (int n = s + sub; n < e; n += 4) sum += in[(size_t)n * HID + c];
    red[sub * HID + c] = sum;
    __syncthreads();
    if (sub == 0)
        stat[c] = (red[c] + red[HID + c] + red[2 * HID + c] + red[3 * HID + c]) / cnt * gms[c];
    __syncthreads();
    float mean = stat[c];

    float vs = 0.f;
    for (int n = s + sub; n < e; n += 4) {
        float hc = in[(size_t)n * HID + c] - mean;
        vs += hc * hc;
    }
    red[sub * HID + c] = vs;
    __syncthreads();
    if (sub == 0) {
        float var = (red[c] + red[HID + c] + red[2 * HID + c] + red[3 * HID + c]) / cnt;
        stat[c] = rsqrtf(var + EPSV);
    }
    __syncthreads();
    float w = gw[c] * stat[c];
    float b = gb[c];

    float pool = 0.f;
    for (int n = s + sub; n < e; n += 4) {
        float v = fmaxf((in[(size_t)n * HID + c] - mean) * w + b, 0.f);
        out[(size_t)n * HID + c] = v;
        if (out2) out2[(size_t)n * HID + c] = v;
        pool += v;
    }
    if (do_pool) {
        __syncthreads();
        red[sub * HID + c] = pool;
        __syncthreads();
        if (sub == 0)
            d_g[g * HID + c] = red[c] + red[HID + c] + red[2 * HID + c] + red[3 * HID + c];
    }
}

// ---------------- output head ----------------
__global__ __launch_bounds__(128) void head_kernel(
    const float* __restrict__ fw1, const float* __restrict__ fb1,
    const float* __restrict__ fw2, const float* __restrict__ fb2,
    float* __restrict__ outp)
{
    int i = blockIdx.x;
    int c = threadIdx.x;
    __shared__ float gs[HID];
    __shared__ float red[HID];
    gs[c] = d_g[i * HID + c];
    __syncthreads();
    float acc = fb1[c];
    #pragma unroll 4
    for (int k = 0; k < HID; k++) acc += gs[k] * fw1[k * HID + c];
    red[c] = fmaxf(acc, 0.f) * fw2[c];
    __syncthreads();
    for (int s = 64; s > 0; s >>= 1) {
        if (c < s) red[c] += red[c + s];
        __syncthreads();
    }
    if (c == 0) outp[i] = red[0] + fb2[0];
}

// ---------------- launch ----------------
extern "C" void kernel_launch(void* const* d_in, const int* in_sizes, int n_in,
                              void* d_out, int out_size)
{
    const float* x     = (const float*)d_in[0];
    const int*   ei    = (const int*)d_in[1];
    const float* ea    = (const float*)d_in[2];
    const int*   batch = (const int*)d_in[3];
    const float* lig_w1 = (const float*)d_in[4];
    const float* lig_b1 = (const float*)d_in[5];
    const float* lig_w2 = (const float*)d_in[6];
    const float* lig_b2 = (const float*)d_in[7];
    const float* prot_w1 = (const float*)d_in[8];
    const float* prot_b1 = (const float*)d_in[9];
    const float* prot_w2 = (const float*)d_in[10];
    const float* prot_b2 = (const float*)d_in[11];
    const float* edge_w = (const float*)d_in[12];
    const float* edge_b = (const float*)d_in[13];
    const float* nn_w1 = (const float*)d_in[14];
    const float* nn_b1 = (const float*)d_in[15];
    const float* nn_w2 = (const float*)d_in[16];
    const float* nn_b2 = (const float*)d_in[17];
    const float* gn_w = (const float*)d_in[18];
    const float* gn_b = (const float*)d_in[19];
    const float* gn_ms = (const float*)d_in[20];
    const float* fc_w1 = (const float*)d_in[21];
    const float* fc_b1 = (const float*)d_in[22];
    const float* fc_w2 = (const float*)d_in[23];
    const float* fc_b2 = (const float*)d_in[24];
    float* outp = (float*)d_out;

    float* hptr = nullptr; float* tptr = nullptr;
    cudaGetSymbolAddress((void**)&hptr, d_h);
    cudaGetSymbolAddress((void**)&tptr, d_t);

    const int SMEM_MLP = 4 * 128 * ASTR * (int)sizeof(__nv_bfloat16);  // 135168 B
    const int SMEM_MSG = 4 * 128 * EASTR * (int)sizeof(__nv_bfloat16)
                       + 128 * ESTR * (int)sizeof(float);              // 20480 + 67584 = 88064 B
    cudaFuncSetAttribute(mlp_mma<IND, 1, true>,  cudaFuncAttributeMaxDynamicSharedMemorySize, SMEM_MLP);
    cudaFuncSetAttribute(mlp_mma<IND, 2, true>,  cudaFuncAttributeMaxDynamicSharedMemorySize, SMEM_MLP);
    cudaFuncSetAttribute(mlp_mma<HID, 0, false>, cudaFuncAttributeMaxDynamicSharedMemorySize, SMEM_MLP);
    cudaFuncSetAttribute(msg_mma, cudaFuncAttributeMaxDynamicSharedMemorySize, SMEM_MSG);

    offsets_kernel<<<1, 256>>>(batch);

    dim3 gB((NN + 127) / 128);  // 391 blocks
    // encoders write h AND seed aggr buffer (t) with h  — msg_mma is launch #4 (ncu window)
    mlp_mma<IND, 1, true><<<gB, 256, SMEM_MLP>>>(x, NN, lig_w1, lig_b1, lig_w2, lig_b2, x, hptr, tptr);
    mlp_mma<IND, 2, true><<<gB, 256, SMEM_MLP>>>(x, NN, prot_w1, prot_b1, prot_w2, prot_b2, x, hptr, tptr);

    for (int l = 0; l < 3; l++) {
        msg_mma<<<NE / 128, 256, SMEM_MSG>>>(ei, ea,
                                             edge_w + (size_t)l * ED * HID,
                                             edge_b + (size_t)l * HID,
                                             hptr, tptr);
        mlp_mma<HID, 0, false><<<gB, 256, SMEM_MLP>>>(
            tptr, NN,
            nn_w1 + (size_t)l * HID * HID, nn_b1 + (size_t)l * HID,
            nn_w2 + (size_t)l * HID * HID, nn_b2 + (size_t)l * HID,
            nullptr, tptr, nullptr);
        gnorm_kernel<<<GG, 512>>>(tptr, hptr, (l < 2) ? tptr : nullptr,
                                  gn_w + (size_t)l * HID, gn_b + (size_t)l * HID,
                                  gn_ms + (size_t)l * HID, (l == 2) ? 1 : 0);
    }

    head_kernel<<<GG, 128>>>(fc_w1, fc_b1, fc_w2, fc_b2, outp);
}

// round 15
// speedup vs baseline: 1.7350x; 1.0984x over previous
#include <cuda_runtime.h>
#include <cuda_bf16.h>
#include <cuda_fp16.h>
#include <stdint.h>
#include <math.h>

#define NN 50000
#define NE 800000
#define IND 64
#define ED 16
#define HID 128
#define GG 128
#define EPSV 1e-5f
#define ASTR 132   // padded smem row stride for 128-wide tiles (bf16 elems)
#define EASTR 20   // padded smem row stride for 16-wide edge tiles (bf16 elems)
#define ESTR 132   // E half row stride (halves)

// ---------------- scratch (no allocations allowed) ----------------
__device__ float d_h[(size_t)NN * HID];   // node features
__device__ float d_t[(size_t)NN * HID];   // aggr / mlp buffer
__device__ float d_g[GG * HID];           // pooled per-graph
__device__ int   d_off[GG + 1];           // graph segment offsets

// ---------------- graph offsets (batch is sorted int32) ----------------
__global__ void offsets_kernel(const int* __restrict__ batch) {
    int g = blockIdx.x * blockDim.x + threadIdx.x;
    if (g > GG) return;
    int lo = 0, hi = NN;
    while (lo < hi) {
        int mid = (lo + hi) >> 1;
        if (batch[mid] < g) lo = mid + 1; else hi = mid;
    }
    d_off[g] = lo;
}

// ---------------- bf16 split + mma helpers ----------------
__device__ __forceinline__ void bsplit(float x, __nv_bfloat16& h, __nv_bfloat16& l) {
    h = __float2bfloat16_rn(x);
    l = __float2bfloat16_rn(x - __bfloat162float(h));
}

__device__ __forceinline__ void mma_bf16(float c[4], const uint32_t a[4], const uint32_t b[2]) {
    asm volatile(
        "mma.sync.aligned.m16n8k16.row.col.f32.bf16.bf16.f32 "
        "{%0,%1,%2,%3}, {%4,%5,%6,%7}, {%8,%9}, {%0,%1,%2,%3};"
        : "+f"(c[0]), "+f"(c[1]), "+f"(c[2]), "+f"(c[3])
        : "r"(a[0]), "r"(a[1]), "r"(a[2]), "r"(a[3]), "r"(b[0]), "r"(b[1]));
}

// warp computes 32x64 of C += A[32 x 16*nch] * W^T, bf16x3 compensated.
__device__ __forceinline__ void warp_gemm(
    const __nv_bfloat16* __restrict__ Ah, const __nv_bfloat16* __restrict__ Al,
    const __nv_bfloat16* __restrict__ Wh, const __nv_bfloat16* __restrict__ Wl,
    int nch, int astr, int r0, int c0, int grp, int qp, float C[2][8][4])
{
    for (int ch = 0; ch < nch; ch++) {
        const int kc = ch * 16 + qp * 2;
        uint32_t ah[2][4], al[2][4];
        #pragma unroll
        for (int mt = 0; mt < 2; mt++) {
            const __nv_bfloat16* p = Ah + (r0 + mt * 16 + grp) * astr + kc;
            const __nv_bfloat16* q = Al + (r0 + mt * 16 + grp) * astr + kc;
            ah[mt][0] = *(const uint32_t*)p;
            ah[mt][1] = *(const uint32_t*)(p + 8 * astr);
            ah[mt][2] = *(const uint32_t*)(p + 8);
            ah[mt][3] = *(const uint32_t*)(p + 8 * astr + 8);
            al[mt][0] = *(const uint32_t*)q;
            al[mt][1] = *(const uint32_t*)(q + 8 * astr);
            al[mt][2] = *(const uint32_t*)(q + 8);
            al[mt][3] = *(const uint32_t*)(q + 8 * astr + 8);
        }
        #pragma unroll
        for (int nt = 0; nt < 8; nt++) {
            const __nv_bfloat16* p = Wh + (c0 + nt * 8 + grp) * astr + kc;
            const __nv_bfloat16* q = Wl + (c0 + nt * 8 + grp) * astr + kc;
            uint32_t bh[2] = { *(const uint32_t*)p, *(const uint32_t*)(p + 8) };
            uint32_t bl[2] = { *(const uint32_t*)q, *(const uint32_t*)(q + 8) };
            #pragma unroll
            for (int mt = 0; mt < 2; mt++) {
                mma_bf16(C[mt][nt], ah[mt], bh);
                mma_bf16(C[mt][nt], ah[mt], bl);
                mma_bf16(C[mt][nt], al[mt], bh);
            }
        }
    }
}

// ---------------- edge message via tensor cores ----------------
// Tile of 128 edges per CTA: E = ea_tile @ W + b (mma, spilled fp16), then
// aggr[dst] += relu(h[src] + E_row)  via red.v4  (aggr pre-seeded with h).
__global__ __launch_bounds__(256, 3) void msg_mma(
    const int* __restrict__ ei, const float* __restrict__ ea,
    const float* __restrict__ ew, const float* __restrict__ eb,
    const float* __restrict__ h, float* __restrict__ aggr)
{
    extern __shared__ char smraw[];
    __nv_bfloat16* Ah = (__nv_bfloat16*)smraw;         // ea tile hi  [128][EASTR]
    __nv_bfloat16* Al = Ah + 128 * EASTR;              // ea tile lo
    __nv_bfloat16* Wh = Al + 128 * EASTR;              // W^T hi      [128 n][EASTR k]
    __nv_bfloat16* Wl = Wh + 128 * EASTR;              // W^T lo
    __half* E = (__half*)(Wl + 128 * EASTR);           // E fp16      [128][ESTR]

    const int tid = threadIdx.x;
    const int ebase = blockIdx.x * 128;

    // load ea tile [128][16] -> bf16 hi/lo
    for (int i = tid; i < 128 * 4; i += 256) {
        int r = i >> 2, k4 = (i & 3) * 4;
        float4 v = *(const float4*)(ea + (size_t)(ebase + r) * ED + k4);
        __nv_bfloat16 h0, l0, h1, l1, h2, l2, h3, l3;
        bsplit(v.x, h0, l0); bsplit(v.y, h1, l1);
        bsplit(v.z, h2, l2); bsplit(v.w, h3, l3);
        *(__nv_bfloat162*)&Ah[r * EASTR + k4]     = __halves2bfloat162(h0, h1);
        *(__nv_bfloat162*)&Ah[r * EASTR + k4 + 2] = __halves2bfloat162(h2, h3);
        *(__nv_bfloat162*)&Al[r * EASTR + k4]     = __halves2bfloat162(l0, l1);
        *(__nv_bfloat162*)&Al[r * EASTR + k4 + 2] = __halves2bfloat162(l2, l3);
    }
    // load W [16][128] transposed -> Wt[n][k] hi/lo
    for (int i = tid; i < 16 * 32; i += 256) {
        int k = i >> 5, n = (i & 31) * 4;
        float4 v = *(const float4*)(ew + (size_t)k * HID + n);
        __nv_bfloat16 hh, ll;
        bsplit(v.x, hh, ll); Wh[(n + 0) * EASTR + k] = hh; Wl[(n + 0) * EASTR + k] = ll;
        bsplit(v.y, hh, ll); Wh[(n + 1) * EASTR + k] = hh; Wl[(n + 1) * EASTR + k] = ll;
        bsplit(v.z, hh, ll); Wh[(n + 2) * EASTR + k] = hh; Wl[(n + 2) * EASTR + k] = ll;
        bsplit(v.w, hh, ll); Wh[(n + 3) * EASTR + k] = hh; Wl[(n + 3) * EASTR + k] = ll;
    }
    __syncthreads();

    const int lane = tid & 31, wid = tid >> 5;
    const int r0 = (wid & 3) * 32, c0 = (wid >> 2) * 64;
    const int grp = lane >> 2, qp = lane & 3;

    float C[2][8][4];
    #pragma unroll
    for (int nt = 0; nt < 8; nt++) {
        float2 bv = *(const float2*)(eb + c0 + nt * 8 + qp * 2);
        #pragma unroll
        for (int mt = 0; mt < 2; mt++) {
            C[mt][nt][0] = bv.x; C[mt][nt][1] = bv.y;
            C[mt][nt][2] = bv.x; C[mt][nt][3] = bv.y;
        }
    }
    warp_gemm(Ah, Al, Wh, Wl, 1, EASTR, r0, c0, grp, qp, C);

    // spill E fragments to fp16 smem
    #pragma unroll
    for (int mt = 0; mt < 2; mt++) {
        int row = r0 + mt * 16 + grp;
        #pragma unroll
        for (int nt = 0; nt < 8; nt++) {
            int col = c0 + nt * 8 + qp * 2;
            *(__half2*)&E[row * ESTR + col]       = __floats2half2_rn(C[mt][nt][0], C[mt][nt][1]);
            *(__half2*)&E[(row + 8) * ESTR + col] = __floats2half2_rn(C[mt][nt][2], C[mt][nt][3]);
        }
    }

    // preload this warp's 16 src + 16 dst indices (1 coalesced load + shfl)
    int rbase = wid * 16;
    int myidx = (lane < 16) ? ei[ebase + rbase + lane]
                            : ei[NE + ebase + rbase + (lane - 16)];
    __syncthreads();

    // epilogue: warp owns edges [rbase, rbase+16), h prefetched 1 ahead
    const float4* h4 = (const float4*)h;
    int src = __shfl_sync(0xffffffffu, myidx, 0);
    float4 hv = h4[(size_t)src * 32 + lane];
    #pragma unroll 4
    for (int i = 0; i < 16; i++) {
        int dst = __shfl_sync(0xffffffffu, myidx, 16 + i);
        float4 hn;
        if (i < 15) {
            int sn = __shfl_sync(0xffffffffu, myidx, i + 1);
            hn = h4[(size_t)sn * 32 + lane];
        }
        __half2 p0 = *(__half2*)&E[(rbase + i) * ESTR + lane * 4];
        __half2 p1 = *(__half2*)&E[(rbase + i) * ESTR + lane * 4 + 2];
        float2 f0 = __half22float2(p0);
        float2 f1 = __half22float2(p1);
        float vx = fmaxf(hv.x + f0.x, 0.f);
        float vy = fmaxf(hv.y + f0.y, 0.f);
        float vz = fmaxf(hv.z + f1.x, 0.f);
        float vw = fmaxf(hv.w + f1.y, 0.f);
        float* ap = aggr + (size_t)dst * HID + lane * 4;
        asm volatile("red.global.add.v4.f32 [%0], {%1, %2, %3, %4};"
                     :: "l"(ap), "f"(vx), "f"(vy), "f"(vz), "f"(vw) : "memory");
        hv = hn;
    }
}

// ---------------- fused 2-layer MLP via tensor cores ----------------
template <int KD, int MODE, bool RELU_OUT>
__global__ __launch_bounds__(256) void mlp_mma(
    const float* __restrict__ in, int nrows,
    const float* __restrict__ w1, const float* __restrict__ b1,
    const float* __restrict__ w2, const float* __restrict__ b2,
    const float* __restrict__ xflag,
    float* __restrict__ out, float* __restrict__ out2)
{
    extern __shared__ __nv_bfloat16 smb[];
    __nv_bfloat16* Ah = smb;
    __nv_bfloat16* Al = Ah + 128 * ASTR;
    __nv_bfloat16* Wh = Al + 128 * ASTR;
    __nv_bfloat16* Wl = Wh + 128 * ASTR;

    const int tid = threadIdx.x;
    const int row0 = blockIdx.x * 128;

    for (int i = tid; i < 128 * (KD / 4); i += 256) {
        int r = i / (KD / 4), k4 = (i % (KD / 4)) * 4;
        float4 v = make_float4(0.f, 0.f, 0.f, 0.f);
        int gr = row0 + r;
        if (gr < nrows) v = *(const float4*)(in + (size_t)gr * KD + k4);
        __nv_bfloat16 h0, l0, h1, l1, h2, l2, h3, l3;
        bsplit(v.x, h0, l0); bsplit(v.y, h1, l1);
        bsplit(v.z, h2, l2); bsplit(v.w, h3, l3);
        *(__nv_bfloat162*)&Ah[r * ASTR + k4]     = __halves2bfloat162(h0, h1);
        *(__nv_bfloat162*)&Ah[r * ASTR + k4 + 2] = __halves2bfloat162(h2, h3);
        *(__nv_bfloat162*)&Al[r * ASTR + k4]     = __halves2bfloat162(l0, l1);
        *(__nv_bfloat162*)&Al[r * ASTR + k4 + 2] = __halves2bfloat162(l2, l3);
    }
    for (int i = tid; i < KD * 32; i += 256) {
        int k = i / 32, n = (i % 32) * 4;
        float4 v = *(const float4*)(w1 + (size_t)k * HID + n);
        __nv_bfloat16 h, l;
        bsplit(v.x, h, l); Wh[(n + 0) * ASTR + k] = h; Wl[(n + 0) * ASTR + k] = l;
        bsplit(v.y, h, l); Wh[(n + 1) * ASTR + k] = h; Wl[(n + 1) * ASTR + k] = l;
        bsplit(v.z, h, l); Wh[(n + 2) * ASTR + k] = h; Wl[(n + 2) * ASTR + k] = l;
        bsplit(v.w, h, l); Wh[(n + 3) * ASTR + k] = h; Wl[(n + 3) * ASTR + k] = l;
    }
    __syncthreads();

    const int lane = tid & 31, wid = tid >> 5;
    const int r0 = (wid & 3) * 32, c0 = (wid >> 2) * 64;
    const int grp = lane >> 2, qp = lane & 3;

    float C[2][8][4];
    #pragma unroll
    for (int nt = 0; nt < 8; nt++) {
        float2 bv = *(const float2*)(b1 + c0 + nt * 8 + qp * 2);
        #pragma unroll
        for (int mt = 0; mt < 2; mt++) {
            C[mt][nt][0] = bv.x; C[mt][nt][1] = bv.y;
            C[mt][nt][2] = bv.x; C[mt][nt][3] = bv.y;
        }
    }
    warp_gemm(Ah, Al, Wh, Wl, KD / 16, ASTR, r0, c0, grp, qp, C);
    __syncthreads();

    #pragma unroll
    for (int mt = 0; mt < 2; mt++) {
        int row = r0 + mt * 16 + grp;
        #pragma unroll
        for (int nt = 0; nt < 8; nt++) {
            int col = c0 + nt * 8 + qp * 2;
            float v0 = fmaxf(C[mt][nt][0], 0.f), v1 = fmaxf(C[mt][nt][1], 0.f);
            float v2 = fmaxf(C[mt][nt][2], 0.f), v3 = fmaxf(C[mt][nt][3], 0.f);
            __nv_bfloat16 ha, la, hb, lb;
            bsplit(v0, ha, la); bsplit(v1, hb, lb);
            *(__nv_bfloat162*)&Ah[row * ASTR + col] = __halves2bfloat162(ha, hb);
            *(__nv_bfloat162*)&Al[row * ASTR + col] = __halves2bfloat162(la, lb);
            bsplit(v2, ha, la); bsplit(v3, hb, lb);
            *(__nv_bfloat162*)&Ah[(row + 8) * ASTR + col] = __halves2bfloat162(ha, hb);
            *(__nv_bfloat162*)&Al[(row + 8) * ASTR + col] = __halves2bfloat162(la, lb);
        }
    }
    for (int i = tid; i < HID * 32; i += 256) {
        int k = i / 32, n = (i % 32) * 4;
        float4 v = *(const float4*)(w2 + (size_t)k * HID + n);
        __nv_bfloat16 h, l;
        bsplit(v.x, h, l); Wh[(n + 0) * ASTR + k] = h; Wl[(n + 0) * ASTR + k] = l;
        bsplit(v.y, h, l); Wh[(n + 1) * ASTR + k] = h; Wl[(n + 1) * ASTR + k] = l;
        bsplit(v.z, h, l); Wh[(n + 2) * ASTR + k] = h; Wl[(n + 2) * ASTR + k] = l;
        bsplit(v.w, h, l); Wh[(n + 3) * ASTR + k] = h; Wl[(n + 3) * ASTR + k] = l;
    }
    __syncthreads();

    #pragma unroll
    for (int nt = 0; nt < 8; nt++) {
        float2 bv = *(const float2*)(b2 + c0 + nt * 8 + qp * 2);
        #pragma unroll
        for (int mt = 0; mt < 2; mt++) {
            C[mt][nt][0] = bv.x; C[mt][nt][1] = bv.y;
            C[mt][nt][2] = bv.x; C[mt][nt][3] = bv.y;
        }
    }
    warp_gemm(Ah, Al, Wh, Wl, HID / 16, ASTR, r0, c0, grp, qp, C);

    #pragma unroll
    for (int mt = 0; mt < 2; mt++) {
        #pragma unroll
        for (int rh = 0; rh < 2; rh++) {
            int gr = row0 + r0 + mt * 16 + grp + rh * 8;
            if (gr >= nrows) continue;
            if (MODE == 1) { if (xflag[(size_t)gr * IND + (IND - 1)] > 0.5f) continue; }
            if (MODE == 2) { if (!(xflag[(size_t)gr * IND + (IND - 1)] > 0.5f)) continue; }
            #pragma unroll
            for (int nt = 0; nt < 8; nt++) {
                int col = c0 + nt * 8 + qp * 2;
                float v0 = C[mt][nt][rh * 2 + 0], v1 = C[mt][nt][rh * 2 + 1];
                if (RELU_OUT) { v0 = fmaxf(v0, 0.f); v1 = fmaxf(v1, 0.f); }
                float2 o = make_float2(v0, v1);
                *(float2*)(out + (size_t)gr * HID + col) = o;
                if (out2) *(float2*)(out2 + (size_t)gr * HID + col) = o;
            }
        }
    }
}

// ---------------- GraphNorm (+ optional pool, + seed next-layer aggr) ----------------
__global__ __launch_bounds__(512) void gnorm_kernel(
    const float* __restrict__ in, float* __restrict__ out,
    float* __restrict__ out2,
    const float* __restrict__ gw, const float* __restrict__ gb,
    const float* __restrict__ gms, int do_pool)
{
    __shared__ float red[4 * HID];
    __shared__ float stat[HID];
    int g = blockIdx.x;
    int tid = threadIdx.x;
    int c = tid & (HID - 1);
    int sub = tid >> 7;
    int s = d_off[g], e = d_off[g + 1];
    float cnt = fmaxf((float)(e - s), 1.f);

    float sum = 0.f;
    for (int n = s + sub; n < e; n += 4) sum += in[(size_t)n * HID + c];
    red[sub * HID + c] = sum;
    __syncthreads();
    if (sub == 0)
        stat[c] = (red[c] + red[HID + c] + red[2 * HID + c] + red[3 * HID + c]) / cnt * gms[c];
    __syncthreads();
    float mean = stat[c];

    float vs = 0.f;
    for (int n = s + sub; n < e; n += 4) {
        float hc = in[(size_t)n * HID + c] - mean;
        vs += hc * hc;
    }
    red[sub * HID + c] = vs;
    __syncthreads();
    if (sub == 0) {
        float var = (red[c] + red[HID + c] + red[2 * HID + c] + red[3 * HID + c]) / cnt;
        stat[c] = rsqrtf(var + EPSV);
    }
    __syncthreads();
    float w = gw[c] * stat[c];
    float b = gb[c];

    float pool = 0.f;
    for (int n = s + sub; n < e; n += 4) {
        float v = fmaxf((in[(size_t)n * HID + c] - mean) * w + b, 0.f);
        out[(size_t)n * HID + c] = v;
        if (out2) out2[(size_t)n * HID + c] = v;
        pool += v;
    }
    if (do_pool) {
        __syncthreads();
        red[sub * HID + c] = pool;
        __syncthreads();
        if (sub == 0)
            d_g[g * HID + c] = red[c] + red[HID + c] + red[2 * HID + c] + red[3 * HID + c];
    }
}

// ---------------- output head ----------------
__global__ __launch_bounds__(128) void head_kernel(
    const float* __restrict__ fw1, const float* __restrict__ fb1,
    const float* __restrict__ fw2, const float* __restrict__ fb2,
    float* __restrict__ outp)
{
    int i = blockIdx.x;
    int c = threadIdx.x;
    __shared__ float gs[HID];
    __shared__ float red[HID];
    gs[c] = d_g[i * HID + c];
    __syncthreads();
    float acc = fb1[c];
    #pragma unroll 4
    for (int k = 0; k < HID; k++) acc += gs[k] * fw1[k * HID + c];
    red[c] = fmaxf(acc, 0.f) * fw2[c];
    __syncthreads();
    for (int s = 64; s > 0; s >>= 1) {
        if (c < s) red[c] += red[c + s];
        __syncthreads();
    }
    if (c == 0) outp[i] = red[0] + fb2[0];
}

// ---------------- launch ----------------
extern "C" void kernel_launch(void* const* d_in, const int* in_sizes, int n_in,
                              void* d_out, int out_size)
{
    const float* x     = (const float*)d_in[0];
    const int*   ei    = (const int*)d_in[1];
    const float* ea    = (const float*)d_in[2];
    const int*   batch = (const int*)d_in[3];
    const float* lig_w1 = (const float*)d_in[4];
    const float* lig_b1 = (const float*)d_in[5];
    const float* lig_w2 = (const float*)d_in[6];
    const float* lig_b2 = (const float*)d_in[7];
    const float* prot_w1 = (const float*)d_in[8];
    const float* prot_b1 = (const float*)d_in[9];
    const float* prot_w2 = (const float*)d_in[10];
    const float* prot_b2 = (const float*)d_in[11];
    const float* edge_w = (const float*)d_in[12];
    const float* edge_b = (const float*)d_in[13];
    const float* nn_w1 = (const float*)d_in[14];
    const float* nn_b1 = (const float*)d_in[15];
    const float* nn_w2 = (const float*)d_in[16];
    const float* nn_b2 = (const float*)d_in[17];
    const float* gn_w = (const float*)d_in[18];
    const float* gn_b = (const float*)d_in[19];
    const float* gn_ms = (const float*)d_in[20];
    const float* fc_w1 = (const float*)d_in[21];
    const float* fc_b1 = (const float*)d_in[22];
    const float* fc_w2 = (const float*)d_in[23];
    const float* fc_b2 = (const float*)d_in[24];
    float* outp = (float*)d_out;

    float* hptr = nullptr; float* tptr = nullptr;
    cudaGetSymbolAddress((void**)&hptr, d_h);
    cudaGetSymbolAddress((void**)&tptr, d_t);

    const int SMEM_MLP = 4 * 128 * ASTR * (int)sizeof(__nv_bfloat16);  // 135168 B
    const int SMEM_MSG = 4 * 128 * EASTR * (int)sizeof(__nv_bfloat16)
                       + 128 * ESTR * (int)sizeof(__half);             // 20480 + 33792 = 54272 B
    cudaFuncSetAttribute(mlp_mma<IND, 1, true>,  cudaFuncAttributeMaxDynamicSharedMemorySize, SMEM_MLP);
    cudaFuncSetAttribute(mlp_mma<IND, 2, true>,  cudaFuncAttributeMaxDynamicSharedMemorySize, SMEM_MLP);
    cudaFuncSetAttribute(mlp_mma<HID, 0, false>, cudaFuncAttributeMaxDynamicSharedMemorySize, SMEM_MLP);
    cudaFuncSetAttribute(msg_mma, cudaFuncAttributeMaxDynamicSharedMemorySize, SMEM_MSG);

    offsets_kernel<<<1, 256>>>(batch);

    dim3 gB((NN + 127) / 128);  // 391 blocks
    // encoders write h AND seed aggr buffer (t) with h  — msg_mma is launch #4 (ncu window)
    mlp_mma<IND, 1, true><<<gB, 256, SMEM_MLP>>>(x, NN, lig_w1, lig_b1, lig_w2, lig_b2, x, hptr, tptr);
    mlp_mma<IND, 2, true><<<gB, 256, SMEM_MLP>>>(x, NN, prot_w1, prot_b1, prot_w2, prot_b2, x, hptr, tptr);

    for (int l = 0; l < 3; l++) {
        msg_mma<<<NE / 128, 256, SMEM_MSG>>>(ei, ea,
                                             edge_w + (size_t)l * ED * HID,
                                             edge_b + (size_t)l * HID,
                                             hptr, tptr);
        mlp_mma<HID, 0, false><<<gB, 256, SMEM_MLP>>>(
            tptr, NN,
            nn_w1 + (size_t)l * HID * HID, nn_b1 + (size_t)l * HID,
            nn_w2 + (size_t)l * HID * HID, nn_b2 + (size_t)l * HID,
            nullptr, tptr, nullptr);
        gnorm_kernel<<<GG, 512>>>(tptr, hptr, (l < 2) ? tptr : nullptr,
                                  gn_w + (size_t)l * HID, gn_b + (size_t)l * HID,
                                  gn_ms + (size_t)l * HID, (l == 2) ? 1 : 0);
    }

    head_kernel<<<GG, 128>>>(fc_w1, fc_b1, fc_w2, fc_b2, outp);
}

// round 16
// speedup vs baseline: 1.8807x; 1.0840x over previous
#include <cuda_runtime.h>
#include <cuda_bf16.h>
#include <cuda_fp16.h>
#include <stdint.h>
#include <math.h>

#define NN 50000
#define NE 800000
#define IND 64
#define ED 16
#define HID 128
#define GG 128
#define EPSV 1e-5f
#define ASTR 132   // padded smem row stride for 128-wide A tiles (bf16 elems)
#define WSTR 66    // padded smem row stride for 64-k W tiles (bf16 elems, 132B rows)
#define EASTR 20   // padded smem row stride for 16-wide edge tiles (bf16 elems)
#define ESTR 132   // E half row stride (halves)

// ---------------- scratch (no allocations allowed) ----------------
__device__ float d_h[(size_t)NN * HID];   // node features
__device__ float d_t[(size_t)NN * HID];   // aggr / mlp buffer
__device__ float d_g[GG * HID];           // pooled per-graph
__device__ int   d_off[GG + 1];           // graph segment offsets

// ---------------- graph offsets (batch is sorted int32) ----------------
__global__ void offsets_kernel(const int* __restrict__ batch) {
    int g = blockIdx.x * blockDim.x + threadIdx.x;
    if (g > GG) return;
    int lo = 0, hi = NN;
    while (lo < hi) {
        int mid = (lo + hi) >> 1;
        if (batch[mid] < g) lo = mid + 1; else hi = mid;
    }
    d_off[g] = lo;
}

// ---------------- bf16 split + mma helpers ----------------
__device__ __forceinline__ void bsplit(float x, __nv_bfloat16& h, __nv_bfloat16& l) {
    h = __float2bfloat16_rn(x);
    l = __float2bfloat16_rn(x - __bfloat162float(h));
}

__device__ __forceinline__ void mma_bf16(float c[4], const uint32_t a[4], const uint32_t b[2]) {
    asm volatile(
        "mma.sync.aligned.m16n8k16.row.col.f32.bf16.bf16.f32 "
        "{%0,%1,%2,%3}, {%4,%5,%6,%7}, {%8,%9}, {%0,%1,%2,%3};"
        : "+f"(c[0]), "+f"(c[1]), "+f"(c[2]), "+f"(c[3])
        : "r"(a[0]), "r"(a[1]), "r"(a[2]), "r"(a[3]), "r"(b[0]), "r"(b[1]));
}

// warp computes 32x64 of C += A[32 x akoff+16*nch] * W^T, bf16x3 compensated.
// A: [row][k] stride astr (hi/lo), k read from akoff. W: [n][k_local] stride wstr.
__device__ __forceinline__ void warp_gemm(
    const __nv_bfloat16* __restrict__ Ah, const __nv_bfloat16* __restrict__ Al,
    const __nv_bfloat16* __restrict__ Wh, const __nv_bfloat16* __restrict__ Wl,
    int nch, int astr, int wstr, int akoff,
    int r0, int c0, int grp, int qp, float C[2][8][4])
{
    for (int ch = 0; ch < nch; ch++) {
        const int kcA = akoff + ch * 16 + qp * 2;
        const int kcW = ch * 16 + qp * 2;
        uint32_t ah[2][4], al[2][4];
        #pragma unroll
        for (int mt = 0; mt < 2; mt++) {
            const __nv_bfloat16* p = Ah + (r0 + mt * 16 + grp) * astr + kcA;
            const __nv_bfloat16* q = Al + (r0 + mt * 16 + grp) * astr + kcA;
            ah[mt][0] = *(const uint32_t*)p;
            ah[mt][1] = *(const uint32_t*)(p + 8 * astr);
            ah[mt][2] = *(const uint32_t*)(p + 8);
            ah[mt][3] = *(const uint32_t*)(p + 8 * astr + 8);
            al[mt][0] = *(const uint32_t*)q;
            al[mt][1] = *(const uint32_t*)(q + 8 * astr);
            al[mt][2] = *(const uint32_t*)(q + 8);
            al[mt][3] = *(const uint32_t*)(q + 8 * astr + 8);
        }
        #pragma unroll
        for (int nt = 0; nt < 8; nt++) {
            const __nv_bfloat16* p = Wh + (c0 + nt * 8 + grp) * wstr + kcW;
            const __nv_bfloat16* q = Wl + (c0 + nt * 8 + grp) * wstr + kcW;
            uint32_t bh[2] = { *(const uint32_t*)p, *(const uint32_t*)(p + 8) };
            uint32_t bl[2] = { *(const uint32_t*)q, *(const uint32_t*)(q + 8) };
            #pragma unroll
            for (int mt = 0; mt < 2; mt++) {
                mma_bf16(C[mt][nt], ah[mt], bh);
                mma_bf16(C[mt][nt], ah[mt], bl);
                mma_bf16(C[mt][nt], al[mt], bh);
            }
        }
    }
}

// load 64 k-rows of W [k][128] transposed into Wt[n][k_local] hi/lo (stride WSTR)
__device__ __forceinline__ void load_wt64(
    const float* __restrict__ w, int krow0,
    __nv_bfloat16* Wh, __nv_bfloat16* Wl, int tid)
{
    for (int i = tid; i < 64 * 32; i += 256) {
        int k = i >> 5, n = (i & 31) * 4;
        float4 v = *(const float4*)(w + (size_t)(krow0 + k) * HID + n);
        __nv_bfloat16 hh, ll;
        bsplit(v.x, hh, ll); Wh[(n + 0) * WSTR + k] = hh; Wl[(n + 0) * WSTR + k] = ll;
        bsplit(v.y, hh, ll); Wh[(n + 1) * WSTR + k] = hh; Wl[(n + 1) * WSTR + k] = ll;
        bsplit(v.z, hh, ll); Wh[(n + 2) * WSTR + k] = hh; Wl[(n + 2) * WSTR + k] = ll;
        bsplit(v.w, hh, ll); Wh[(n + 3) * WSTR + k] = hh; Wl[(n + 3) * WSTR + k] = ll;
    }
}

// ---------------- edge message via tensor cores ----------------
// Tile of 128 edges per CTA: E = ea_tile @ W + b (mma, spilled fp16), then
// aggr[dst] += relu(h[src] + E_row)  via red.v4  (aggr pre-seeded with h).
__global__ __launch_bounds__(256, 3) void msg_mma(
    const int* __restrict__ ei, const float* __restrict__ ea,
    const float* __restrict__ ew, const float* __restrict__ eb,
    const float* __restrict__ h, float* __restrict__ aggr)
{
    extern __shared__ char smraw[];
    __nv_bfloat16* Ah = (__nv_bfloat16*)smraw;         // ea tile hi  [128][EASTR]
    __nv_bfloat16* Al = Ah + 128 * EASTR;              // ea tile lo
    __nv_bfloat16* Wh = Al + 128 * EASTR;              // W^T hi      [128 n][EASTR k]
    __nv_bfloat16* Wl = Wh + 128 * EASTR;              // W^T lo
    __half* E = (__half*)(Wl + 128 * EASTR);           // E fp16      [128][ESTR]

    const int tid = threadIdx.x;
    const int ebase = blockIdx.x * 128;

    for (int i = tid; i < 128 * 4; i += 256) {
        int r = i >> 2, k4 = (i & 3) * 4;
        float4 v = *(const float4*)(ea + (size_t)(ebase + r) * ED + k4);
        __nv_bfloat16 h0, l0, h1, l1, h2, l2, h3, l3;
        bsplit(v.x, h0, l0); bsplit(v.y, h1, l1);
        bsplit(v.z, h2, l2); bsplit(v.w, h3, l3);
        *(__nv_bfloat162*)&Ah[r * EASTR + k4]     = __halves2bfloat162(h0, h1);
        *(__nv_bfloat162*)&Ah[r * EASTR + k4 + 2] = __halves2bfloat162(h2, h3);
        *(__nv_bfloat162*)&Al[r * EASTR + k4]     = __halves2bfloat162(l0, l1);
        *(__nv_bfloat162*)&Al[r * EASTR + k4 + 2] = __halves2bfloat162(l2, l3);
    }
    for (int i = tid; i < 16 * 32; i += 256) {
        int k = i >> 5, n = (i & 31) * 4;
        float4 v = *(const float4*)(ew + (size_t)k * HID + n);
        __nv_bfloat16 hh, ll;
        bsplit(v.x, hh, ll); Wh[(n + 0) * EASTR + k] = hh; Wl[(n + 0) * EASTR + k] = ll;
        bsplit(v.y, hh, ll); Wh[(n + 1) * EASTR + k] = hh; Wl[(n + 1) * EASTR + k] = ll;
        bsplit(v.z, hh, ll); Wh[(n + 2) * EASTR + k] = hh; Wl[(n + 2) * EASTR + k] = ll;
        bsplit(v.w, hh, ll); Wh[(n + 3) * EASTR + k] = hh; Wl[(n + 3) * EASTR + k] = ll;
    }
    __syncthreads();

    const int lane = tid & 31, wid = tid >> 5;
    const int r0 = (wid & 3) * 32, c0 = (wid >> 2) * 64;
    const int grp = lane >> 2, qp = lane & 3;

    float C[2][8][4];
    #pragma unroll
    for (int nt = 0; nt < 8; nt++) {
        float2 bv = *(const float2*)(eb + c0 + nt * 8 + qp * 2);
        #pragma unroll
        for (int mt = 0; mt < 2; mt++) {
            C[mt][nt][0] = bv.x; C[mt][nt][1] = bv.y;
            C[mt][nt][2] = bv.x; C[mt][nt][3] = bv.y;
        }
    }
    warp_gemm(Ah, Al, Wh, Wl, 1, EASTR, EASTR, 0, r0, c0, grp, qp, C);

    #pragma unroll
    for (int mt = 0; mt < 2; mt++) {
        int row = r0 + mt * 16 + grp;
        #pragma unroll
        for (int nt = 0; nt < 8; nt++) {
            int col = c0 + nt * 8 + qp * 2;
            *(__half2*)&E[row * ESTR + col]       = __floats2half2_rn(C[mt][nt][0], C[mt][nt][1]);
            *(__half2*)&E[(row + 8) * ESTR + col] = __floats2half2_rn(C[mt][nt][2], C[mt][nt][3]);
        }
    }

    int rbase = wid * 16;
    int myidx = (lane < 16) ? ei[ebase + rbase + lane]
                            : ei[NE + ebase + rbase + (lane - 16)];
    __syncthreads();

    const float4* h4 = (const float4*)h;
    int src = __shfl_sync(0xffffffffu, myidx, 0);
    float4 hv = h4[(size_t)src * 32 + lane];
    #pragma unroll 4
    for (int i = 0; i < 16; i++) {
        int dst = __shfl_sync(0xffffffffu, myidx, 16 + i);
        float4 hn;
        if (i < 15) {
            int sn = __shfl_sync(0xffffffffu, myidx, i + 1);
            hn = h4[(size_t)sn * 32 + lane];
        }
        uint2 pe = *(uint2*)&E[(rbase + i) * ESTR + lane * 4];  // 8B aligned (264B rows)
        float2 f0 = __half22float2(*(__half2*)&pe.x);
        float2 f1 = __half22float2(*(__half2*)&pe.y);
        float vx = fmaxf(hv.x + f0.x, 0.f);
        float vy = fmaxf(hv.y + f0.y, 0.f);
        float vz = fmaxf(hv.z + f1.x, 0.f);
        float vw = fmaxf(hv.w + f1.y, 0.f);
        float* ap = aggr + (size_t)dst * HID + lane * 4;
        asm volatile("red.global.add.v4.f32 [%0], {%1, %2, %3, %4};"
                     :: "l"(ap), "f"(vx), "f"(vy), "f"(vz), "f"(vw) : "memory");
        hv = hn;
    }
}

// ---------------- fused 2-layer MLP via tensor cores (2-phase W, 2 CTA/SM) ----------------
template <int KD, int MODE, bool RELU_OUT>
__global__ __launch_bounds__(256, 2) void mlp_mma(
    const float* __restrict__ in, int nrows,
    const float* __restrict__ w1, const float* __restrict__ b1,
    const float* __restrict__ w2, const float* __restrict__ b2,
    const float* __restrict__ xflag,
    float* __restrict__ out, float* __restrict__ out2)
{
    extern __shared__ __nv_bfloat16 smb[];
    __nv_bfloat16* Ah = smb;                 // A tile hi [128][ASTR]
    __nv_bfloat16* Al = Ah + 128 * ASTR;     // A tile lo
    __nv_bfloat16* Wh = Al + 128 * ASTR;     // W^T hi [128 n][WSTR k]  (64-k window)
    __nv_bfloat16* Wl = Wh + 128 * WSTR;     // W^T lo

    const int tid = threadIdx.x;
    const int row0 = blockIdx.x * 128;

    // load input tile [128][KD] fp32 -> bf16 hi/lo
    for (int i = tid; i < 128 * (KD / 4); i += 256) {
        int r = i / (KD / 4), k4 = (i % (KD / 4)) * 4;
        float4 v = make_float4(0.f, 0.f, 0.f, 0.f);
        int gr = row0 + r;
        if (gr < nrows) v = *(const float4*)(in + (size_t)gr * KD + k4);
        __nv_bfloat16 h0, l0, h1, l1, h2, l2, h3, l3;
        bsplit(v.x, h0, l0); bsplit(v.y, h1, l1);
        bsplit(v.z, h2, l2); bsplit(v.w, h3, l3);
        *(__nv_bfloat162*)&Ah[r * ASTR + k4]     = __halves2bfloat162(h0, h1);
        *(__nv_bfloat162*)&Ah[r * ASTR + k4 + 2] = __halves2bfloat162(h2, h3);
        *(__nv_bfloat162*)&Al[r * ASTR + k4]     = __halves2bfloat162(l0, l1);
        *(__nv_bfloat162*)&Al[r * ASTR + k4 + 2] = __halves2bfloat162(l2, l3);
    }
    load_wt64(w1, 0, Wh, Wl, tid);
    __syncthreads();

    const int lane = tid & 31, wid = tid >> 5;
    const int r0 = (wid & 3) * 32, c0 = (wid >> 2) * 64;
    const int grp = lane >> 2, qp = lane & 3;

    float C[2][8][4];
    #pragma unroll
    for (int nt = 0; nt < 8; nt++) {
        float2 bv = *(const float2*)(b1 + c0 + nt * 8 + qp * 2);
        #pragma unroll
        for (int mt = 0; mt < 2; mt++) {
            C[mt][nt][0] = bv.x; C[mt][nt][1] = bv.y;
            C[mt][nt][2] = bv.x; C[mt][nt][3] = bv.y;
        }
    }
    warp_gemm(Ah, Al, Wh, Wl, 4, ASTR, WSTR, 0, r0, c0, grp, qp, C);
    if (KD == 128) {
        __syncthreads();
        load_wt64(w1, 64, Wh, Wl, tid);
        __syncthreads();
        warp_gemm(Ah, Al, Wh, Wl, 4, ASTR, WSTR, 64, r0, c0, grp, qp, C);
    }
    __syncthreads();   // all GEMM1 A/W reads done

    // write relu(h1) back into Ah/Al as new A [128][128]
    #pragma unroll
    for (int mt = 0; mt < 2; mt++) {
        int row = r0 + mt * 16 + grp;
        #pragma unroll
        for (int nt = 0; nt < 8; nt++) {
            int col = c0 + nt * 8 + qp * 2;
            float v0 = fmaxf(C[mt][nt][0], 0.f), v1 = fmaxf(C[mt][nt][1], 0.f);
            float v2 = fmaxf(C[mt][nt][2], 0.f), v3 = fmaxf(C[mt][nt][3], 0.f);
            __nv_bfloat16 ha, la, hb, lb;
            bsplit(v0, ha, la); bsplit(v1, hb, lb);
            *(__nv_bfloat162*)&Ah[row * ASTR + col] = __halves2bfloat162(ha, hb);
            *(__nv_bfloat162*)&Al[row * ASTR + col] = __halves2bfloat162(la, lb);
            bsplit(v2, ha, la); bsplit(v3, hb, lb);
            *(__nv_bfloat162*)&Ah[(row + 8) * ASTR + col] = __halves2bfloat162(ha, hb);
            *(__nv_bfloat162*)&Al[(row + 8) * ASTR + col] = __halves2bfloat162(la, lb);
        }
    }
    __syncthreads();
    load_wt64(w2, 0, Wh, Wl, tid);
    __syncthreads();

    #pragma unroll
    for (int nt = 0; nt < 8; nt++) {
        float2 bv = *(const float2*)(b2 + c0 + nt * 8 + qp * 2);
        #pragma unroll
        for (int mt = 0; mt < 2; mt++) {
            C[mt][nt][0] = bv.x; C[mt][nt][1] = bv.y;
            C[mt][nt][2] = bv.x; C[mt][nt][3] = bv.y;
        }
    }
    warp_gemm(Ah, Al, Wh, Wl, 4, ASTR, WSTR, 0, r0, c0, grp, qp, C);
    __syncthreads();
    load_wt64(w2, 64, Wh, Wl, tid);
    __syncthreads();
    warp_gemm(Ah, Al, Wh, Wl, 4, ASTR, WSTR, 64, r0, c0, grp, qp, C);

    #pragma unroll
    for (int mt = 0; mt < 2; mt++) {
        #pragma unroll
        for (int rh = 0; rh < 2; rh++) {
            int gr = row0 + r0 + mt * 16 + grp + rh * 8;
            if (gr >= nrows) continue;
            if (MODE == 1) { if (xflag[(size_t)gr * IND + (IND - 1)] > 0.5f) continue; }
            if (MODE == 2) { if (!(xflag[(size_t)gr * IND + (IND - 1)] > 0.5f)) continue; }
            #pragma unroll
            for (int nt = 0; nt < 8; nt++) {
                int col = c0 + nt * 8 + qp * 2;
                float v0 = C[mt][nt][rh * 2 + 0], v1 = C[mt][nt][rh * 2 + 1];
                if (RELU_OUT) { v0 = fmaxf(v0, 0.f); v1 = fmaxf(v1, 0.f); }
                float2 o = make_float2(v0, v1);
                *(float2*)(out + (size_t)gr * HID + col) = o;
                if (out2) *(float2*)(out2 + (size_t)gr * HID + col) = o;
            }
        }
    }
}

// ---------------- GraphNorm (+ optional pool, + seed next-layer aggr) ----------------
__global__ __launch_bounds__(512) void gnorm_kernel(
    const float* __restrict__ in, float* __restrict__ out,
    float* __restrict__ out2,
    const float* __restrict__ gw, const float* __restrict__ gb,
    const float* __restrict__ gms, int do_pool)
{
    __shared__ float red[4 * HID];
    __shared__ float stat[HID];
    int g = blockIdx.x;
    int tid = threadIdx.x;
    int c = tid & (HID - 1);
    int sub = tid >> 7;
    int s = d_off[g], e = d_off[g + 1];
    float cnt = fmaxf((float)(e - s), 1.f);

    float sum = 0.f;
    for (int n = s + sub; n < e; n += 4) sum += in[(size_t)n * HID + c];
    red[sub * HID + c] = sum;
    __syncthreads();
    if (sub == 0)
        stat[c] = (red[c] + red[HID + c] + red[2 * HID + c] + red[3 * HID + c]) / cnt * gms[c];
    __syncthreads();
    float mean = stat[c];

    float vs = 0.f;
    for (int n = s + sub; n < e; n += 4) {
        float hc = in[(size_t)n * HID + c] - mean;
        vs += hc * hc;
    }
    red[sub * HID + c] = vs;
    __syncthreads();
    if (sub == 0) {
        float var = (red[c] + red[HID + c] + red[2 * HID + c] + red[3 * HID + c]) / cnt;
        stat[c] = rsqrtf(var + EPSV);
    }
    __syncthreads();
    float w = gw[c] * stat[c];
    float b = gb[c];

    float pool = 0.f;
    for (int n = s + sub; n < e; n += 4) {
        float v = fmaxf((in[(size_t)n * HID + c] - mean) * w + b, 0.f);
        out[(size_t)n * HID + c] = v;
        if (out2) out2[(size_t)n * HID + c] = v;
        pool += v;
    }
    if (do_pool) {
        __syncthreads();
        red[sub * HID + c] = pool;
        __syncthreads();
        if (sub == 0)
            d_g[g * HID + c] = red[c] + red[HID + c] + red[2 * HID + c] + red[3 * HID + c];
    }
}

// ---------------- output head ----------------
__global__ __launch_bounds__(128) void head_kernel(
    const float* __restrict__ fw1, const float* __restrict__ fb1,
    const float* __restrict__ fw2, const float* __restrict__ fb2,
    float* __restrict__ outp)
{
    int i = blockIdx.x;
    int c = threadIdx.x;
    __shared__ float gs[HID];
    __shared__ float red[HID];
    gs[c] = d_g[i * HID + c];
    __syncthreads();
    float acc = fb1[c];
    #pragma unroll 4
    for (int k = 0; k < HID; k++) acc += gs[k] * fw1[k * HID + c];
    red[c] = fmaxf(acc, 0.f) * fw2[c];
    __syncthreads();
    for (int s = 64; s > 0; s >>= 1) {
        if (c < s) red[c] += red[c + s];
        __syncthreads();
    }
    if (c == 0) outp[i] = red[0] + fb2[0];
}

// ---------------- launch ----------------
extern "C" void kernel_launch(void* const* d_in, const int* in_sizes, int n_in,
                              void* d_out, int out_size)
{
    const float* x     = (const float*)d_in[0];
    const int*   ei    = (const int*)d_in[1];
    const float* ea    = (const float*)d_in[2];
    const int*   batch = (const int*)d_in[3];
    const float* lig_w1 = (const float*)d_in[4];
    const float* lig_b1 = (const float*)d_in[5];
    const float* lig_w2 = (const float*)d_in[6];
    const float* lig_b2 = (const float*)d_in[7];
    const float* prot_w1 = (const float*)d_in[8];
    const float* prot_b1 = (const float*)d_in[9];
    const float* prot_w2 = (const float*)d_in[10];
    const float* prot_b2 = (const float*)d_in[11];
    const float* edge_w = (const float*)d_in[12];
    const float* edge_b = (const float*)d_in[13];
    const float* nn_w1 = (const float*)d_in[14];
    const float* nn_b1 = (const float*)d_in[15];
    const float* nn_w2 = (const float*)d_in[16];
    const float* nn_b2 = (const float*)d_in[17];
    const float* gn_w = (const float*)d_in[18];
    const float* gn_b = (const float*)d_in[19];
    const float* gn_ms = (const float*)d_in[20];
    const float* fc_w1 = (const float*)d_in[21];
    const float* fc_b1 = (const float*)d_in[22];
    const float* fc_w2 = (const float*)d_in[23];
    const float* fc_b2 = (const float*)d_in[24];
    float* outp = (float*)d_out;

    float* hptr = nullptr; float* tptr = nullptr;
    cudaGetSymbolAddress((void**)&hptr, d_h);
    cudaGetSymbolAddress((void**)&tptr, d_t);

    const int SMEM_MLP = (2 * 128 * ASTR + 2 * 128 * WSTR) * (int)sizeof(__nv_bfloat16); // 101376 B
    const int SMEM_MSG = 4 * 128 * EASTR * (int)sizeof(__nv_bfloat16)
                       + 128 * ESTR * (int)sizeof(__half);                               // 54272 B
    cudaFuncSetAttribute(mlp_mma<IND, 1, true>,  cudaFuncAttributeMaxDynamicSharedMemorySize, SMEM_MLP);
    cudaFuncSetAttribute(mlp_mma<IND, 2, true>,  cudaFuncAttributeMaxDynamicSharedMemorySize, SMEM_MLP);
    cudaFuncSetAttribute(mlp_mma<HID, 0, false>, cudaFuncAttributeMaxDynamicSharedMemorySize, SMEM_MLP);
    cudaFuncSetAttribute(msg_mma, cudaFuncAttributeMaxDynamicSharedMemorySize, SMEM_MSG);

    offsets_kernel<<<1, 256>>>(batch);

    dim3 gB((NN + 127) / 128);  // 391 blocks
    // encoders write h AND seed aggr buffer (t) with h  — msg_mma is launch #4 (ncu window)
    mlp_mma<IND, 1, true><<<gB, 256, SMEM_MLP>>>(x, NN, lig_w1, lig_b1, lig_w2, lig_b2, x, hptr, tptr);
    mlp_mma<IND, 2, true><<<gB, 256, SMEM_MLP>>>(x, NN, prot_w1, prot_b1, prot_w2, prot_b2, x, hptr, tptr);

    for (int l = 0; l < 3; l++) {
        msg_mma<<<NE / 128, 256, SMEM_MSG>>>(ei, ea,
                                             edge_w + (size_t)l * ED * HID,
                                             edge_b + (size_t)l * HID,
                                             hptr, tptr);
        mlp_mma<HID, 0, false><<<gB, 256, SMEM_MLP>>>(
            tptr, NN,
            nn_w1 + (size_t)l * HID * HID, nn_b1 + (size_t)l * HID,
            nn_w2 + (size_t)l * HID * HID, nn_b2 + (size_t)l * HID,
            nullptr, tptr, nullptr);
        gnorm_kernel<<<GG, 512>>>(tptr, hptr, (l < 2) ? tptr : nullptr,
                                  gn_w + (size_t)l * HID, gn_b + (size_t)l * HID,
                                  gn_ms + (size_t)l * HID, (l == 2) ? 1 : 0);
    }

    head_kernel<<<GG, 128>>>(fc_w1, fc_b1, fc_w2, fc_b2, outp);
}